// round 8
// baseline (speedup 1.0000x reference)
#include <cuda_runtime.h>
#include <cuda_fp16.h>
#include <cstdint>

#define Bd 128
#define Sd 2048
#define Hd 256
#define Ed 256
#define VSZ 32000

// ---------------- scratch (device globals; no allocation) ----------------
__device__ float g_w2h[Bd * Hd];
__device__ float g_mz[2 * 2048];           // per (b,chunk): local max, local sum
__device__ float g_XaP[16 * Bd * Hd];      // per-tile partial numerators
__device__ __align__(16) __half g_h1h[Bd * Hd];

#define PAD_E 72
#define CH_HALF_E (Hd * PAD_E)             // 18432 elems = 36864 B per chunk
__device__ __align__(16) __half g_W1p[4 * CH_HALF_E];
__device__ __align__(16) __half g_Woutp[4 * VSZ * PAD_E];

// ---------------- helpers ----------------
__device__ __forceinline__ float fast_tanh(float x) {
    float y;
    asm("tanh.approx.f32 %0, %1;" : "=f"(y) : "f"(x));
    return y;
}
__device__ __forceinline__ uint32_t smem_u32(const void* p) {
    uint32_t a;
    asm("{ .reg .u64 t; cvta.to.shared.u64 t, %1; cvt.u32.u64 %0, t; }"
        : "=r"(a) : "l"(p));
    return a;
}
__device__ __forceinline__ void cp16(uint32_t dst, const void* src) {
    asm volatile("cp.async.cg.shared.global [%0], [%1], 16;"
                 :: "r"(dst), "l"(src) : "memory");
}
__device__ __forceinline__ void cp_commit() {
    asm volatile("cp.async.commit_group;" ::: "memory");
}
template <int N>
__device__ __forceinline__ void cp_wait() {
    asm volatile("cp.async.wait_group %0;" :: "n"(N) : "memory");
}
__device__ __forceinline__ void mma_fp16(float* d, const uint32_t* a,
                                         uint32_t b0, uint32_t b1) {
    asm volatile(
        "mma.sync.aligned.m16n8k16.row.col.f32.f16.f16.f32 "
        "{%0,%1,%2,%3}, {%4,%5,%6,%7}, {%8,%9}, {%0,%1,%2,%3};"
        : "+f"(d[0]), "+f"(d[1]), "+f"(d[2]), "+f"(d[3])
        : "r"(a[0]), "r"(a[1]), "r"(a[2]), "r"(a[3]), "r"(b0), "r"(b1));
}
__device__ __forceinline__ void ldsm_x4(uint32_t* r, uint32_t addr) {
    asm volatile(
        "ldmatrix.sync.aligned.m8n8.x4.shared.b16 {%0,%1,%2,%3}, [%4];"
        : "=r"(r[0]), "=r"(r[1]), "=r"(r[2]), "=r"(r[3]) : "r"(addr));
}

// ---------------- P0: pack W1 (transpose + fp16, padded) ----------------
__global__ void prep_w1_kernel(const float* __restrict__ W1) {
    int n = blockIdx.x;
    int k = threadIdx.x;
    float x = W1[k * Hd + n];
    int c = k >> 6;
    int kk = k & 63;
    g_W1p[c * CH_HALF_E + n * PAD_E + kk] = __float2half_rn(x);
}

// ---------------- P1: pack Wout -> fp16, chunked + padded ----------------
__global__ void prep_wout_kernel(const float* __restrict__ Wout) {
    int idx4 = (blockIdx.x * 256 + threadIdx.x) * 4;
    int v = idx4 >> 8;
    int k = idx4 & 255;
    float4 x = *(const float4*)(Wout + (size_t)v * Hd + k);
    __half2 a = {__float2half_rn(x.x), __float2half_rn(x.y)};
    __half2 b = {__float2half_rn(x.z), __float2half_rn(x.w)};
    uint2 w;
    w.x = *(uint32_t*)&a;
    w.y = *(uint32_t*)&b;
    *(uint2*)&g_Woutp[(size_t)(k >> 6) * VSZ * PAD_E + (size_t)v * PAD_E + (k & 63)] = w;
}

// ---------------- K1: w2h = hidden[1] @ W2 + b2 ----------------
__global__ void w2h_kernel(const float* __restrict__ hidden,
                           const float* __restrict__ W2,
                           const float* __restrict__ b2) {
    int b = blockIdx.x;
    int tid = threadIdx.x;  // 512
    int k = tid & 255;
    int h = tid >> 8;
    __shared__ float sh[Hd];
    __shared__ float part[512];
    if (tid < Hd) sh[tid] = hidden[(Bd + b) * Hd + tid];
    __syncthreads();
    float acc = 0.f;
#pragma unroll 16
    for (int j = h * 128; j < h * 128 + 128; j++) acc += sh[j] * W2[j * Hd + k];
    part[tid] = acc;
    __syncthreads();
    if (tid < 256) g_w2h[b * Hd + tid] = part[tid] + part[tid + 256] + b2[tid];
}

// ---------------- K2: scores + local softmax + partial Xa numerator -------
// CTA: 128m x 256n, 16 warps (4m x 4n), fp16 mma via ldmatrix fragments.
#define SA_HI 0
#define SB_OFF 67584
#define SB_STRIDE 36864
#define SC_SMEM (67584 + 2 * 36864)
__global__ __launch_bounds__(512, 1)
void scores_mma_kernel(const float* __restrict__ enc,
                       const float* __restrict__ Vv) {
    extern __shared__ __align__(16) char smem[];
    const uint32_t sm_b = smem_u32(smem);
    const int tid = threadIdx.x;
    const int wid = tid >> 5;
    const int lane = tid & 31;
    const int g = lane >> 2;
    const int t = lane & 3;
    const int wm = wid >> 2;
    const int wn = wid & 3;
    const int quad = lane >> 3;
    const int r8 = lane & 7;
    const int b = blockIdx.x >> 4;
    const int chunk = blockIdx.x & 15;
    const int m0 = blockIdx.x * 128;

    float acc[2][8][4];
#pragma unroll
    for (int f = 0; f < 2; f++)
#pragma unroll
        for (int j = 0; j < 8; j++)
#pragma unroll
            for (int q = 0; q < 4; q++) acc[f][j][q] = 0.f;

    // ldmatrix base addresses
    uint32_t aaddr[2];
#pragma unroll
    for (int f = 0; f < 2; f++)
        aaddr[f] = sm_b + (wm * 32 + f * 16 + ((quad & 1) << 3) + r8) * 528
                 + ((quad >> 1) << 4);
    uint32_t bbase[4];
#pragma unroll
    for (int jj = 0; jj < 4; jj++)
        bbase[jj] = (wn * 64 + jj * 16 + ((quad >> 1) << 3) + r8) * 144
                  + ((quad & 1) << 4);

    // ---- issue B stage 0 ----
    {
        const char* src = (const char*)g_W1p;
#pragma unroll
        for (int i = 0; i < 5; i++) {
            int idx = tid + i * 512;
            if (idx < 2304) cp16(sm_b + SB_OFF + idx * 16, src + idx * 16);
        }
        cp_commit();
    }

    // ---- fill A (128 x 256 fp32 -> fp16), overlaps with cp.async ----
    {
        const float* encb = enc + (size_t)m0 * Hd;
#pragma unroll
        for (int i = 0; i < 32; i++) {
            int idx = tid + i * 512;
            int row = idx >> 7;
            int kp = idx & 127;
            float2 v = *(const float2*)(encb + (size_t)row * Hd + kp * 2);
            __half2 hp = {__float2half_rn(v.x), __float2half_rn(v.y)};
            *(uint32_t*)(smem + SA_HI + row * 528 + kp * 4) = *(uint32_t*)&hp;
        }
    }

    // ---- 4 pipelined B stages ----
#pragma unroll
    for (int c = 0; c < 4; c++) {
        if (c < 3) {
            const char* src = (const char*)(g_W1p + (size_t)(c + 1) * CH_HALF_E);
            uint32_t dst = sm_b + SB_OFF + ((c + 1) & 1) * SB_STRIDE;
#pragma unroll
            for (int i = 0; i < 5; i++) {
                int idx = tid + i * 512;
                if (idx < 2304) cp16(dst + idx * 16, src + idx * 16);
            }
            cp_commit();
            cp_wait<1>();
        } else {
            cp_wait<0>();
        }
        __syncthreads();

        const uint32_t buf = sm_b + SB_OFF + (c & 1) * SB_STRIDE;
#pragma unroll
        for (int ks = 0; ks < 4; ks++) {
            uint32_t af[2][4];
#pragma unroll
            for (int f = 0; f < 2; f++)
                ldsm_x4(af[f], aaddr[f] + c * 128 + ks * 32);
#pragma unroll
            for (int jj = 0; jj < 4; jj++) {
                uint32_t bf[4];
                ldsm_x4(bf, buf + bbase[jj] + ks * 32);
                mma_fp16(acc[0][2 * jj], af[0], bf[0], bf[1]);
                mma_fp16(acc[1][2 * jj], af[1], bf[0], bf[1]);
                mma_fp16(acc[0][2 * jj + 1], af[0], bf[2], bf[3]);
                mma_fp16(acc[1][2 * jj + 1], af[1], bf[2], bf[3]);
            }
        }
        __syncthreads();
    }

    // ---- epilogue: scores -> local softmax -> partial numerator ----
    float* EP = (float*)(smem + SB_OFF);
    float* sw2 = EP;
    float* sV = EP + 256;
    float* sp = EP + 512;
    float* red = EP + 1024;
    float* e_arr = EP + 1152;
    float* pN = EP + 1280;
    if (tid < 256) {
        sw2[tid] = g_w2h[b * Hd + tid];
        sV[tid] = Vv[tid];
    }
    __syncthreads();

    float p[2][2] = {{0.f, 0.f}, {0.f, 0.f}};
#pragma unroll
    for (int f = 0; f < 2; f++)
#pragma unroll
        for (int j = 0; j < 8; j++) {
            int cc = wn * 64 + 8 * j + 2 * t;
            float v0 = sV[cc], v1 = sV[cc + 1];
            float w0 = sw2[cc], w1 = sw2[cc + 1];
            p[f][0] += v0 * fast_tanh(acc[f][j][0] + w0)
                     + v1 * fast_tanh(acc[f][j][1] + w1);
            p[f][1] += v0 * fast_tanh(acc[f][j][2] + w0)
                     + v1 * fast_tanh(acc[f][j][3] + w1);
        }
#pragma unroll
    for (int f = 0; f < 2; f++)
#pragma unroll
        for (int u = 0; u < 2; u++) {
            float v = p[f][u];
            v += __shfl_xor_sync(0xffffffffu, v, 1);
            v += __shfl_xor_sync(0xffffffffu, v, 2);
            if (t == 0) {
                int r = wm * 32 + f * 16 + g + 8 * u;
                sp[wn * 128 + r] = v;
            }
        }
    __syncthreads();

    float sc = 0.f;
    if (tid < 128) {
        sc = sp[tid] + sp[128 + tid] + sp[256 + tid] + sp[384 + tid];
        red[tid] = sc;
    }
    __syncthreads();
    for (int d = 64; d > 0; d >>= 1) {
        if (tid < d) red[tid] = fmaxf(red[tid], red[tid + d]);
        __syncthreads();
    }
    float mloc = red[0];
    __syncthreads();
    if (tid < 128) {
        float e = expf(sc - mloc);
        e_arr[tid] = e;
        red[tid] = e;
    }
    __syncthreads();
    for (int d = 64; d > 0; d >>= 1) {
        if (tid < d) red[tid] += red[tid + d];
        __syncthreads();
    }
    if (tid == 0) {
        g_mz[2 * blockIdx.x] = mloc;
        g_mz[2 * blockIdx.x + 1] = red[0];
    }

    int half_id = tid >> 8;
    int h = tid & 255;
    float a2 = 0.f;
#pragma unroll 8
    for (int s = half_id * 64; s < half_id * 64 + 64; s++) {
        __half hv = *(const __half*)(smem + SA_HI + s * 528 + h * 2);
        a2 += e_arr[s] * __half2float(hv);
    }
    pN[half_id * 256 + h] = a2;
    __syncthreads();
    if (tid < 256)
        g_XaP[((size_t)chunk * Bd + b) * Hd + tid] = pN[tid] + pN[256 + tid];
}

// ---------------- K4: fused Xa-combine + res + GRU0 + GRU1 (4 b / CTA) ----
#define PB 4
__global__ __launch_bounds__(768)
void post_kernel(const int* __restrict__ inp,
                 const float* __restrict__ emb,
                 const float* __restrict__ W3,
                 const float* __restrict__ b3,
                 const float* __restrict__ hidden,
                 const float* __restrict__ Wih0,
                 const float* __restrict__ Whh0,
                 const float* __restrict__ bih0,
                 const float* __restrict__ bhh0,
                 const float* __restrict__ Wih1,
                 const float* __restrict__ Whh1,
                 const float* __restrict__ bih1,
                 const float* __restrict__ bhh1,
                 float* __restrict__ hid_out) {
    const int b0 = blockIdx.x * PB;
    const int tid = threadIdx.x;  // 768
    __shared__ float cat[PB][512];
    __shared__ float sx[PB][256], sh[PB][256];
    __shared__ float sgi[PB][768], sgh[PB][768];

    // ---- build concat [emb | Xa-combined] for 4 b ----
    for (int idx = tid; idx < PB * 512; idx += 768) {
        int bb = idx >> 9;
        int j = idx & 511;
        int b = b0 + bb;
        if (j < 256) {
            int token = inp[b];
            cat[bb][j] = emb[(size_t)token * Ed + j];
        } else {
            int hh = j - 256;
            float M = -1e30f;
#pragma unroll
            for (int i = 0; i < 16; i++)
                M = fmaxf(M, g_mz[2 * (b * 16 + i)]);
            float Z = 0.f, X = 0.f;
#pragma unroll
            for (int i = 0; i < 16; i++) {
                float w = expf(g_mz[2 * (b * 16 + i)] - M);
                Z += w * g_mz[2 * (b * 16 + i) + 1];
                X += w * g_XaP[((size_t)i * Bd + b) * Hd + hh];
            }
            cat[bb][j] = X / Z;
        }
    }
    __syncthreads();

    // ---- res = cat @ W3 + b3 ----
    for (int idx = tid; idx < PB * 256; idx += 768) {
        int bb = idx >> 8;
        int k = idx & 255;
        float acc = b3[k];
#pragma unroll 8
        for (int j = 0; j < 512; j++) acc += cat[bb][j] * W3[j * Hd + k];
        sx[bb][k] = acc;
        sh[bb][k] = hidden[(size_t)(b0 + bb) * Hd + k];
    }
    __syncthreads();

    // ---- two GRU cells ----
#pragma unroll
    for (int cell = 0; cell < 2; cell++) {
        const float* Wih = cell ? Wih1 : Wih0;
        const float* Whh = cell ? Whh1 : Whh0;
        const float* bih = cell ? bih1 : bih0;
        const float* bhh = cell ? bhh1 : bhh0;
        {
            float gi[PB], gh[PB];
#pragma unroll
            for (int bb = 0; bb < PB; bb++) {
                gi[bb] = bih[tid];
                gh[bb] = bhh[tid];
            }
            const float4* wi = (const float4*)(Wih + (size_t)tid * Hd);
            const float4* wh = (const float4*)(Whh + (size_t)tid * Hd);
#pragma unroll 8
            for (int q = 0; q < Hd / 4; q++) {
                float4 a = wi[q];
                float4 c = wh[q];
#pragma unroll
                for (int bb = 0; bb < PB; bb++) {
                    float4 xv = *(const float4*)&sx[bb][q * 4];
                    float4 hv = *(const float4*)&sh[bb][q * 4];
                    gi[bb] += a.x * xv.x + a.y * xv.y + a.z * xv.z + a.w * xv.w;
                    gh[bb] += c.x * hv.x + c.y * hv.y + c.z * hv.z + c.w * hv.w;
                }
            }
#pragma unroll
            for (int bb = 0; bb < PB; bb++) {
                sgi[bb][tid] = gi[bb];
                sgh[bb][tid] = gh[bb];
            }
        }
        __syncthreads();
        for (int idx = tid; idx < PB * 256; idx += 768) {
            int bb = idx >> 8;
            int j = idx & 255;
            float r = 1.f / (1.f + expf(-(sgi[bb][j] + sgh[bb][j])));
            float z = 1.f / (1.f + expf(-(sgi[bb][Hd + j] + sgh[bb][Hd + j])));
            float n = tanhf(sgi[bb][2 * Hd + j] + r * sgh[bb][2 * Hd + j]);
            float hn = (1.f - z) * n + z * sh[bb][j];
            hid_out[((size_t)cell * Bd + b0 + bb) * Hd + j] = hn;
            if (cell == 0) {
                cat[bb][j] = hn;  // stage h0
            } else {
                g_h1h[(size_t)(b0 + bb) * Hd + j] = __float2half_rn(hn);
            }
        }
        __syncthreads();
        if (cell == 0) {
            for (int idx = tid; idx < PB * 256; idx += 768) {
                int bb = idx >> 8;
                int j = idx & 255;
                sx[bb][j] = cat[bb][j];
                sh[bb][j] = hidden[(size_t)(Bd + b0 + bb) * Hd + j];
            }
            __syncthreads();
        }
    }
}

// ---------------- K7: logits via fp16 mma + ldmatrix ----------------
#define LG_SMEM (67584 + 2 * 36864)
__global__ __launch_bounds__(512, 1)
void logits_mma_kernel(const float* __restrict__ bout,
                       float* __restrict__ out) {
    extern __shared__ __align__(16) char smem[];
    const uint32_t sm_b = smem_u32(smem);
    const int tid = threadIdx.x;
    const int wid = tid >> 5;
    const int lane = tid & 31;
    const int g = lane >> 2;
    const int t = lane & 3;
    const int wm = wid >> 2;
    const int wn = wid & 3;
    const int quad = lane >> 3;
    const int r8 = lane & 7;
    const int v0 = blockIdx.x * 256;

    float acc[2][8][4];
#pragma unroll
    for (int f = 0; f < 2; f++)
#pragma unroll
        for (int j = 0; j < 8; j++)
#pragma unroll
            for (int q = 0; q < 4; q++) acc[f][j][q] = 0.f;

    uint32_t aaddr[2];
#pragma unroll
    for (int f = 0; f < 2; f++)
        aaddr[f] = sm_b + (wm * 32 + f * 16 + ((quad & 1) << 3) + r8) * 528
                 + ((quad >> 1) << 4);
    uint32_t bbase[4];
#pragma unroll
    for (int jj = 0; jj < 4; jj++)
        bbase[jj] = (wn * 64 + jj * 16 + ((quad >> 1) << 3) + r8) * 144
                  + ((quad & 1) << 4);

    // B stage 0
    {
        const char* src = (const char*)(g_Woutp + (size_t)v0 * PAD_E);
#pragma unroll
        for (int i = 0; i < 5; i++) {
            int idx = tid + i * 512;
            if (idx < 2304) cp16(sm_b + SB_OFF + idx * 16, src + idx * 16);
        }
        cp_commit();
    }
    // A fill: g_h1h [128 x 256] half -> padded rows
    {
        const uint32_t* src = (const uint32_t*)g_h1h;
#pragma unroll
        for (int i = 0; i < 32; i++) {
            int idx = tid + i * 512;
            int row = idx >> 7;
            int c32 = idx & 127;
            *(uint32_t*)(smem + row * 528 + c32 * 4) = src[idx];
        }
    }

#pragma unroll
    for (int c = 0; c < 4; c++) {
        if (c < 3) {
            const char* src =
                (const char*)(g_Woutp + ((size_t)(c + 1) * VSZ + v0) * PAD_E);
            uint32_t dst = sm_b + SB_OFF + ((c + 1) & 1) * SB_STRIDE;
#pragma unroll
            for (int i = 0; i < 5; i++) {
                int idx = tid + i * 512;
                if (idx < 2304) cp16(dst + idx * 16, src + idx * 16);
            }
            cp_commit();
            cp_wait<1>();
        } else {
            cp_wait<0>();
        }
        __syncthreads();

        const uint32_t buf = sm_b + SB_OFF + (c & 1) * SB_STRIDE;
#pragma unroll
        for (int ks = 0; ks < 4; ks++) {
            uint32_t af[2][4];
#pragma unroll
            for (int f = 0; f < 2; f++)
                ldsm_x4(af[f], aaddr[f] + c * 128 + ks * 32);
#pragma unroll
            for (int jj = 0; jj < 4; jj++) {
                uint32_t bf[4];
                ldsm_x4(bf, buf + bbase[jj] + ks * 32);
                mma_fp16(acc[0][2 * jj], af[0], bf[0], bf[1]);
                mma_fp16(acc[1][2 * jj], af[1], bf[0], bf[1]);
                mma_fp16(acc[0][2 * jj + 1], af[0], bf[2], bf[3]);
                mma_fp16(acc[1][2 * jj + 1], af[1], bf[2], bf[3]);
            }
        }
        __syncthreads();
    }

    // epilogue: stage 64-col groups, add bout, coalesced store
    float* stage = (float*)(smem + SB_OFF);
#pragma unroll
    for (int cg = 0; cg < 4; cg++) {
        if (wn == cg) {
#pragma unroll
            for (int f = 0; f < 2; f++)
#pragma unroll
                for (int j = 0; j < 8; j++)
#pragma unroll
                    for (int q = 0; q < 4; q++) {
                        int row = wm * 32 + f * 16 + g + 8 * (q >> 1);
                        int col = 8 * j + 2 * t + (q & 1);
                        stage[row * 65 + col] = acc[f][j][q];
                    }
        }
        __syncthreads();
#pragma unroll
        for (int i = 0; i < 16; i++) {
            int idx = tid + i * 512;
            int row = idx >> 6;
            int col = idx & 63;
            out[(size_t)row * VSZ + v0 + cg * 64 + col] =
                stage[row * 65 + col] + bout[v0 + cg * 64 + col];
        }
        __syncthreads();
    }
}

// ---------------- K8: in-place log_softmax over vocab (float4) -----------
__global__ __launch_bounds__(1024)
void logsoftmax_kernel(float* __restrict__ out) {
    const int b = blockIdx.x;
    const int tid = threadIdx.x;  // 1024
    __shared__ float red[1024];
    float4* row4 = (float4*)(out + (size_t)b * VSZ);  // 8000 float4

    float m = -1e30f;
    for (int v = tid; v < 8000; v += 1024) {
        float4 x = row4[v];
        m = fmaxf(m, fmaxf(fmaxf(x.x, x.y), fmaxf(x.z, x.w)));
    }
    red[tid] = m;
    __syncthreads();
    for (int d = 512; d > 0; d >>= 1) {
        if (tid < d) red[tid] = fmaxf(red[tid], red[tid + d]);
        __syncthreads();
    }
    m = red[0];
    __syncthreads();

    float s = 0.f;
    for (int v = tid; v < 8000; v += 1024) {
        float4 x = row4[v];
        s += expf(x.x - m) + expf(x.y - m) + expf(x.z - m) + expf(x.w - m);
    }
    red[tid] = s;
    __syncthreads();
    for (int d = 512; d > 0; d >>= 1) {
        if (tid < d) red[tid] += red[tid + d];
        __syncthreads();
    }
    float lse = m + logf(red[0]);
    for (int v = tid; v < 8000; v += 1024) {
        float4 x = row4[v];
        x.x -= lse; x.y -= lse; x.z -= lse; x.w -= lse;
        row4[v] = x;
    }
}

// ---------------- launch ----------------
extern "C" void kernel_launch(void* const* d_in, const int* in_sizes, int n_in,
                              void* d_out, int out_size) {
    const int* inp = (const int*)d_in[0];
    const float* hidden = (const float*)d_in[1];
    const float* enc = (const float*)d_in[2];
    const float* emb = (const float*)d_in[3];
    const float* W1 = (const float*)d_in[4];
    const float* W2 = (const float*)d_in[5];
    const float* W3 = (const float*)d_in[6];
    const float* b2 = (const float*)d_in[7];
    const float* b3 = (const float*)d_in[8];
    const float* V = (const float*)d_in[9];
    const float* Wih0 = (const float*)d_in[10];
    const float* Whh0 = (const float*)d_in[11];
    const float* bih0 = (const float*)d_in[12];
    const float* bhh0 = (const float*)d_in[13];
    const float* Wih1 = (const float*)d_in[14];
    const float* Whh1 = (const float*)d_in[15];
    const float* bih1 = (const float*)d_in[16];
    const float* bhh1 = (const float*)d_in[17];
    const float* Wout = (const float*)d_in[18];
    const float* bout = (const float*)d_in[19];

    float* out = (float*)d_out;
    float* hid_out = out + (size_t)Bd * VSZ;

    cudaFuncSetAttribute(scores_mma_kernel,
                         cudaFuncAttributeMaxDynamicSharedMemorySize, SC_SMEM);
    cudaFuncSetAttribute(logits_mma_kernel,
                         cudaFuncAttributeMaxDynamicSharedMemorySize, LG_SMEM);

    prep_w1_kernel<<<Hd, Hd>>>(W1);
    prep_wout_kernel<<<8000, 256>>>(Wout);
    w2h_kernel<<<Bd, 512>>>(hidden, W2, b2);
    scores_mma_kernel<<<Bd * 16, 512, SC_SMEM>>>(enc, V);
    post_kernel<<<Bd / PB, 768>>>(inp, emb, W3, b3, hidden,
                                  Wih0, Whh0, bih0, bhh0,
                                  Wih1, Whh1, bih1, bhh1, hid_out);
    logits_mma_kernel<<<VSZ / 256, 512, LG_SMEM>>>(bout, out);
    logsoftmax_kernel<<<Bd, 1024>>>(out);
}

// round 9
// speedup vs baseline: 1.1896x; 1.1896x over previous
#include <cuda_runtime.h>
#include <cuda_fp16.h>
#include <cstdint>

#define Bd 128
#define Sd 2048
#define Hd 256
#define Ed 256
#define VSZ 32000

// ---------------- scratch (device globals; no allocation) ----------------
__device__ float g_w2h[Bd * Hd];
__device__ float g_mz[2 * 2048];           // per (b,chunk): local max, local sum
__device__ float g_XaP[16 * Bd * Hd];      // per-tile partial numerators
__device__ __align__(16) __half g_h1h[Bd * Hd];

#define PAD_E 72
#define CH_HALF_E (Hd * PAD_E)             // 18432 elems = 36864 B per chunk
__device__ __align__(16) __half g_W1p[4 * CH_HALF_E];
__device__ __align__(16) __half g_Woutp[4 * VSZ * PAD_E];

// ---------------- helpers ----------------
__device__ __forceinline__ float fast_tanh(float x) {
    float y;
    asm("tanh.approx.f32 %0, %1;" : "=f"(y) : "f"(x));
    return y;
}
__device__ __forceinline__ uint32_t smem_u32(const void* p) {
    uint32_t a;
    asm("{ .reg .u64 t; cvta.to.shared.u64 t, %1; cvt.u32.u64 %0, t; }"
        : "=r"(a) : "l"(p));
    return a;
}
__device__ __forceinline__ void cp16(uint32_t dst, const void* src) {
    asm volatile("cp.async.cg.shared.global [%0], [%1], 16;"
                 :: "r"(dst), "l"(src) : "memory");
}
__device__ __forceinline__ void cp_commit() {
    asm volatile("cp.async.commit_group;" ::: "memory");
}
template <int N>
__device__ __forceinline__ void cp_wait() {
    asm volatile("cp.async.wait_group %0;" :: "n"(N) : "memory");
}
__device__ __forceinline__ void mma_fp16(float* d, const uint32_t* a,
                                         uint32_t b0, uint32_t b1) {
    asm volatile(
        "mma.sync.aligned.m16n8k16.row.col.f32.f16.f16.f32 "
        "{%0,%1,%2,%3}, {%4,%5,%6,%7}, {%8,%9}, {%0,%1,%2,%3};"
        : "+f"(d[0]), "+f"(d[1]), "+f"(d[2]), "+f"(d[3])
        : "r"(a[0]), "r"(a[1]), "r"(a[2]), "r"(a[3]), "r"(b0), "r"(b1));
}
__device__ __forceinline__ void ldsm_x4(uint32_t* r, uint32_t addr) {
    asm volatile(
        "ldmatrix.sync.aligned.m8n8.x4.shared.b16 {%0,%1,%2,%3}, [%4];"
        : "=r"(r[0]), "=r"(r[1]), "=r"(r[2]), "=r"(r[3]) : "r"(addr));
}

// ---------------- P0: pack W1 (transpose + fp16, padded) ----------------
__global__ void prep_w1_kernel(const float* __restrict__ W1) {
    int n = blockIdx.x;
    int k = threadIdx.x;
    float x = W1[k * Hd + n];
    int c = k >> 6;
    int kk = k & 63;
    g_W1p[c * CH_HALF_E + n * PAD_E + kk] = __float2half_rn(x);
}

// ---------------- P1: pack Wout -> fp16, chunked + padded ----------------
__global__ void prep_wout_kernel(const float* __restrict__ Wout) {
    int idx4 = (blockIdx.x * 256 + threadIdx.x) * 4;
    int v = idx4 >> 8;
    int k = idx4 & 255;
    float4 x = *(const float4*)(Wout + (size_t)v * Hd + k);
    __half2 a = {__float2half_rn(x.x), __float2half_rn(x.y)};
    __half2 b = {__float2half_rn(x.z), __float2half_rn(x.w)};
    uint2 w;
    w.x = *(uint32_t*)&a;
    w.y = *(uint32_t*)&b;
    *(uint2*)&g_Woutp[(size_t)(k >> 6) * VSZ * PAD_E + (size_t)v * PAD_E + (k & 63)] = w;
}

// ---------------- K1: w2h = hidden[1] @ W2 + b2 ----------------
__global__ void w2h_kernel(const float* __restrict__ hidden,
                           const float* __restrict__ W2,
                           const float* __restrict__ b2) {
    int b = blockIdx.x;
    int tid = threadIdx.x;  // 512
    int k = tid & 255;
    int h = tid >> 8;
    __shared__ float sh[Hd];
    __shared__ float part[512];
    if (tid < Hd) sh[tid] = hidden[(Bd + b) * Hd + tid];
    __syncthreads();
    float acc = 0.f;
#pragma unroll 16
    for (int j = h * 128; j < h * 128 + 128; j++) acc += sh[j] * W2[j * Hd + k];
    part[tid] = acc;
    __syncthreads();
    if (tid < 256) g_w2h[b * Hd + tid] = part[tid] + part[tid + 256] + b2[tid];
}

// ---------------- K2: scores + local softmax + partial Xa numerator -------
// CTA: 128m x 256n, 16 warps (4m x 4n). fp16 mma + ldmatrix.
// Intra-CTA pipeline: A fp32 chunks cp.async -> staging (x2), convert to
// fp16 A; B chunks cp.async (x2); chunk c+1/c+2 loads overlap chunk-c mma.
#define SA_HI 0
#define SB_OFF 67584
#define SB_STRIDE 36864
#define SAS_OFF 141312
#define SAS_STRIDE 32768
#define SC_SMEM (141312 + 2 * 32768)
__global__ __launch_bounds__(512, 1)
void scores_mma_kernel(const float* __restrict__ enc,
                       const float* __restrict__ Vv) {
    extern __shared__ __align__(16) char smem[];
    const uint32_t sm_b = smem_u32(smem);
    const int tid = threadIdx.x;
    const int wid = tid >> 5;
    const int lane = tid & 31;
    const int g = lane >> 2;
    const int t = lane & 3;
    const int wm = wid >> 2;
    const int wn = wid & 3;
    const int quad = lane >> 3;
    const int r8 = lane & 7;
    const int b = blockIdx.x >> 4;
    const int chunk = blockIdx.x & 15;
    const int m0 = blockIdx.x * 128;
    const float* encb = enc + (size_t)m0 * Hd;

    float acc[2][8][4];
#pragma unroll
    for (int f = 0; f < 2; f++)
#pragma unroll
        for (int j = 0; j < 8; j++)
#pragma unroll
            for (int q = 0; q < 4; q++) acc[f][j][q] = 0.f;

    uint32_t aaddr[2];
#pragma unroll
    for (int f = 0; f < 2; f++)
        aaddr[f] = sm_b + (wm * 32 + f * 16 + ((quad & 1) << 3) + r8) * 528
                 + ((quad >> 1) << 4);
    uint32_t bbase[4];
#pragma unroll
    for (int jj = 0; jj < 4; jj++)
        bbase[jj] = (wn * 64 + jj * 16 + ((quad >> 1) << 3) + r8) * 144
                  + ((quad & 1) << 4);

    // issue A-chunk c (fp32, 32KB) into staging buffer sb
#define ISSUE_A(c, sb)                                                        \
    {                                                                         \
        _Pragma("unroll") for (int i = 0; i < 4; i++) {                       \
            int idx = tid + i * 512;                                          \
            int row = idx >> 4;                                               \
            int seg = idx & 15;                                               \
            cp16(sm_b + SAS_OFF + (sb)*SAS_STRIDE + row * 256 + seg * 16,     \
                 encb + (size_t)row * Hd + (c)*64 + seg * 4);                 \
        }                                                                     \
    }
    // issue B-chunk c (fp16, 36864B) into B buffer bb
#define ISSUE_B(c, bb)                                                        \
    {                                                                         \
        const char* srcB = (const char*)(g_W1p + (size_t)(c)*CH_HALF_E);      \
        _Pragma("unroll") for (int i = 0; i < 5; i++) {                       \
            int idx = tid + i * 512;                                          \
            if (idx < 2304)                                                   \
                cp16(sm_b + SB_OFF + (bb)*SB_STRIDE + idx * 16,               \
                     srcB + idx * 16);                                        \
        }                                                                     \
    }
    // convert staging (fp32) -> fp16 A columns of chunk c
#define CONVERT_A(c)                                                          \
    {                                                                         \
        _Pragma("unroll") for (int i = 0; i < 8; i++) {                       \
            int idx = tid + i * 512;                                          \
            int row = idx >> 5;                                               \
            int kp2 = idx & 31;                                               \
            float2 v = *(const float2*)(smem + SAS_OFF + ((c)&1) * SAS_STRIDE \
                                        + row * 256 + kp2 * 8);               \
            __half2 hp = {__float2half_rn(v.x), __float2half_rn(v.y)};        \
            *(uint32_t*)(smem + row * 528 + (c)*128 + kp2 * 4) =              \
                *(uint32_t*)&hp;                                              \
        }                                                                     \
    }
#define MMA_CHUNK(c)                                                          \
    {                                                                         \
        const uint32_t buf = sm_b + SB_OFF + ((c)&1) * SB_STRIDE;             \
        _Pragma("unroll") for (int ks = 0; ks < 4; ks++) {                    \
            uint32_t af[2][4];                                                \
            _Pragma("unroll") for (int f = 0; f < 2; f++)                     \
                ldsm_x4(af[f], aaddr[f] + (c)*128 + ks * 32);                 \
            _Pragma("unroll") for (int jj = 0; jj < 4; jj++) {                \
                uint32_t bf[4];                                               \
                ldsm_x4(bf, buf + bbase[jj] + ks * 32);                       \
                mma_fp16(acc[0][2 * jj], af[0], bf[0], bf[1]);                \
                mma_fp16(acc[1][2 * jj], af[1], bf[0], bf[1]);                \
                mma_fp16(acc[0][2 * jj + 1], af[0], bf[2], bf[3]);            \
                mma_fp16(acc[1][2 * jj + 1], af[1], bf[2], bf[3]);            \
            }                                                                 \
        }                                                                     \
    }

    // ---- prologue: G1={A0,B0}, G2={A1,B1} ----
    ISSUE_A(0, 0); ISSUE_B(0, 0); cp_commit();
    ISSUE_A(1, 1); ISSUE_B(1, 1); cp_commit();

    // ---- c=0 ----
    cp_wait<1>();            // G1 done
    __syncthreads();
    CONVERT_A(0);
    __syncthreads();         // stage0 free, A fp16 chunk0 visible
    ISSUE_A(2, 0); cp_commit();   // G3
    MMA_CHUNK(0);
    // ---- c=1 ----
    cp_wait<1>();            // G2 done (G3 pending)
    __syncthreads();         // all threads done mma c0 -> buf0 free
    ISSUE_A(3, 1);           // stage1 free (convert1 below reads it first? no:
                             // A3 goes to stage1 AFTER convert1 -> reorder:
    // NOTE: convert1 must read stage1 before A3 overwrites it.
    // So: convert first, sync, then issue.
    CONVERT_A(1);
    __syncthreads();
    ISSUE_B(2, 0); cp_commit();   // G4 = {A3(!), B2}
    MMA_CHUNK(1);
    // ---- c=2 ----
    cp_wait<0>();            // G3(A2) + G4(A3,B2) done
    __syncthreads();         // mma c1 done -> buf1 free
    ISSUE_B(3, 1); cp_commit();   // G5
    CONVERT_A(2);
    __syncthreads();
    MMA_CHUNK(2);
    // ---- c=3 ----
    cp_wait<0>();            // G5 done
    __syncthreads();         // mma c2 done
    CONVERT_A(3);
    __syncthreads();
    MMA_CHUNK(3);

    // ---- epilogue: scores -> local softmax -> partial numerator ----
    __syncthreads();
    float* EP = (float*)(smem + SB_OFF);
    float* sw2 = EP;
    float* sV = EP + 256;
    float* sp = EP + 512;
    float* red = EP + 1024;
    float* e_arr = EP + 1152;
    float* pN = EP + 1280;
    if (tid < 256) {
        sw2[tid] = g_w2h[b * Hd + tid];
        sV[tid] = Vv[tid];
    }
    __syncthreads();

    float p[2][2] = {{0.f, 0.f}, {0.f, 0.f}};
#pragma unroll
    for (int f = 0; f < 2; f++)
#pragma unroll
        for (int j = 0; j < 8; j++) {
            int cc = wn * 64 + 8 * j + 2 * t;
            float v0 = sV[cc], v1 = sV[cc + 1];
            float w0 = sw2[cc], w1 = sw2[cc + 1];
            p[f][0] += v0 * fast_tanh(acc[f][j][0] + w0)
                     + v1 * fast_tanh(acc[f][j][1] + w1);
            p[f][1] += v0 * fast_tanh(acc[f][j][2] + w0)
                     + v1 * fast_tanh(acc[f][j][3] + w1);
        }
#pragma unroll
    for (int f = 0; f < 2; f++)
#pragma unroll
        for (int u = 0; u < 2; u++) {
            float v = p[f][u];
            v += __shfl_xor_sync(0xffffffffu, v, 1);
            v += __shfl_xor_sync(0xffffffffu, v, 2);
            if (t == 0) {
                int r = wm * 32 + f * 16 + g + 8 * u;
                sp[wn * 128 + r] = v;
            }
        }
    __syncthreads();

    float sc = 0.f;
    if (tid < 128) {
        sc = sp[tid] + sp[128 + tid] + sp[256 + tid] + sp[384 + tid];
        red[tid] = sc;
    }
    __syncthreads();
    for (int d = 64; d > 0; d >>= 1) {
        if (tid < d) red[tid] = fmaxf(red[tid], red[tid + d]);
        __syncthreads();
    }
    float mloc = red[0];
    __syncthreads();
    if (tid < 128) {
        float e = expf(sc - mloc);
        e_arr[tid] = e;
        red[tid] = e;
    }
    __syncthreads();
    for (int d = 64; d > 0; d >>= 1) {
        if (tid < d) red[tid] += red[tid + d];
        __syncthreads();
    }
    if (tid == 0) {
        g_mz[2 * blockIdx.x] = mloc;
        g_mz[2 * blockIdx.x + 1] = red[0];
    }

    int half_id = tid >> 8;
    int h = tid & 255;
    float a2 = 0.f;
#pragma unroll 8
    for (int s = half_id * 64; s < half_id * 64 + 64; s++) {
        __half hv = *(const __half*)(smem + SA_HI + s * 528 + h * 2);
        a2 += e_arr[s] * __half2float(hv);
    }
    pN[half_id * 256 + h] = a2;
    __syncthreads();
    if (tid < 256)
        g_XaP[((size_t)chunk * Bd + b) * Hd + tid] = pN[tid] + pN[256 + tid];
}

// ---------------- K4: fused Xa-combine + res + GRU0 + GRU1 (per-b) -------
__global__ __launch_bounds__(768)
void post_kernel(const int* __restrict__ inp,
                 const float* __restrict__ emb,
                 const float* __restrict__ W3,
                 const float* __restrict__ b3,
                 const float* __restrict__ hidden,
                 const float* __restrict__ Wih0,
                 const float* __restrict__ Whh0,
                 const float* __restrict__ bih0,
                 const float* __restrict__ bhh0,
                 const float* __restrict__ Wih1,
                 const float* __restrict__ Whh1,
                 const float* __restrict__ bih1,
                 const float* __restrict__ bhh1,
                 float* __restrict__ hid_out) {
    const int b = blockIdx.x;
    const int tid = threadIdx.x;  // 768
    __shared__ float cat[Ed + Hd];
    __shared__ float part[512];
    __shared__ float sgi[768], sgh[768];
    __shared__ float sx[Hd], sh[Hd];

    int token = inp[b];
    if (tid < Ed) {
        cat[tid] = emb[(size_t)token * Ed + tid];
    } else if (tid < Ed + Hd) {
        int hh = tid - Ed;
        float M = -1e30f;
#pragma unroll
        for (int i = 0; i < 16; i++)
            M = fmaxf(M, g_mz[2 * (b * 16 + i)]);
        float Z = 0.f, X = 0.f;
#pragma unroll
        for (int i = 0; i < 16; i++) {
            float w = expf(g_mz[2 * (b * 16 + i)] - M);
            Z += w * g_mz[2 * (b * 16 + i) + 1];
            X += w * g_XaP[((size_t)i * Bd + b) * Hd + hh];
        }
        cat[tid] = X / Z;
    }
    __syncthreads();
    if (tid < 512) {
        int k = tid & 255;
        int h = tid >> 8;
        float acc = 0.f;
#pragma unroll 16
        for (int j = h * 256; j < h * 256 + 256; j++)
            acc += cat[j] * W3[j * Hd + k];
        part[tid] = acc;
    }
    __syncthreads();
    if (tid < 256) {
        sx[tid] = part[tid] + part[tid + 256] + b3[tid];
        sh[tid] = hidden[b * Hd + tid];
    }
    __syncthreads();

#pragma unroll
    for (int cell = 0; cell < 2; cell++) {
        const float* Wih = cell ? Wih1 : Wih0;
        const float* Whh = cell ? Whh1 : Whh0;
        const float* bih = cell ? bih1 : bih0;
        const float* bhh = cell ? bhh1 : bhh0;
        {
            int gidx = tid;
            const float4* wi = (const float4*)(Wih + (size_t)gidx * Hd);
            const float4* wh = (const float4*)(Whh + (size_t)gidx * Hd);
            float gi = bih[gidx], gh = bhh[gidx];
#pragma unroll 16
            for (int q = 0; q < Hd / 4; q++) {
                float4 a = wi[q];
                float4 c = wh[q];
                float4 xv = *(const float4*)&sx[q * 4];
                float4 hv = *(const float4*)&sh[q * 4];
                gi += a.x * xv.x + a.y * xv.y + a.z * xv.z + a.w * xv.w;
                gh += c.x * hv.x + c.y * hv.y + c.z * hv.z + c.w * hv.w;
            }
            sgi[gidx] = gi;
            sgh[gidx] = gh;
        }
        __syncthreads();
        if (tid < 256) {
            int j = tid;
            float r = 1.f / (1.f + expf(-(sgi[j] + sgh[j])));
            float z = 1.f / (1.f + expf(-(sgi[Hd + j] + sgh[Hd + j])));
            float n = tanhf(sgi[2 * Hd + j] + r * sgh[2 * Hd + j]);
            float hn = (1.f - z) * n + z * sh[j];
            hid_out[((size_t)cell * Bd + b) * Hd + j] = hn;
            if (cell == 0) {
                part[j] = hn;
            } else {
                g_h1h[b * Hd + j] = __float2half_rn(hn);
            }
        }
        __syncthreads();
        if (cell == 0 && tid < 256) {
            sx[tid] = part[tid];
            sh[tid] = hidden[(Bd + b) * Hd + tid];
        }
        __syncthreads();
    }
}

// ---------------- K7: logits via fp16 mma + ldmatrix ----------------
#define LG_SMEM (67584 + 2 * 36864)
__global__ __launch_bounds__(512, 1)
void logits_mma_kernel(const float* __restrict__ bout,
                       float* __restrict__ out) {
    extern __shared__ __align__(16) char smem[];
    const uint32_t sm_b = smem_u32(smem);
    const int tid = threadIdx.x;
    const int wid = tid >> 5;
    const int lane = tid & 31;
    const int g = lane >> 2;
    const int t = lane & 3;
    const int wm = wid >> 2;
    const int wn = wid & 3;
    const int quad = lane >> 3;
    const int r8 = lane & 7;
    const int v0 = blockIdx.x * 256;

    float acc[2][8][4];
#pragma unroll
    for (int f = 0; f < 2; f++)
#pragma unroll
        for (int j = 0; j < 8; j++)
#pragma unroll
            for (int q = 0; q < 4; q++) acc[f][j][q] = 0.f;

    uint32_t aaddr[2];
#pragma unroll
    for (int f = 0; f < 2; f++)
        aaddr[f] = sm_b + (wm * 32 + f * 16 + ((quad & 1) << 3) + r8) * 528
                 + ((quad >> 1) << 4);
    uint32_t bbase[4];
#pragma unroll
    for (int jj = 0; jj < 4; jj++)
        bbase[jj] = (wn * 64 + jj * 16 + ((quad >> 1) << 3) + r8) * 144
                  + ((quad & 1) << 4);

    {
        const char* src = (const char*)(g_Woutp + (size_t)v0 * PAD_E);
#pragma unroll
        for (int i = 0; i < 5; i++) {
            int idx = tid + i * 512;
            if (idx < 2304) cp16(sm_b + SB_OFF + idx * 16, src + idx * 16);
        }
        cp_commit();
    }
    {
        const uint32_t* src = (const uint32_t*)g_h1h;
#pragma unroll
        for (int i = 0; i < 32; i++) {
            int idx = tid + i * 512;
            int row = idx >> 7;
            int c32 = idx & 127;
            *(uint32_t*)(smem + row * 528 + c32 * 4) = src[idx];
        }
    }

#pragma unroll
    for (int c = 0; c < 4; c++) {
        if (c < 3) {
            const char* src =
                (const char*)(g_Woutp + ((size_t)(c + 1) * VSZ + v0) * PAD_E);
            uint32_t dst = sm_b + SB_OFF + ((c + 1) & 1) * SB_STRIDE;
#pragma unroll
            for (int i = 0; i < 5; i++) {
                int idx = tid + i * 512;
                if (idx < 2304) cp16(dst + idx * 16, src + idx * 16);
            }
            cp_commit();
            cp_wait<1>();
        } else {
            cp_wait<0>();
        }
        __syncthreads();

        const uint32_t buf = sm_b + SB_OFF + (c & 1) * SB_STRIDE;
#pragma unroll
        for (int ks = 0; ks < 4; ks++) {
            uint32_t af[2][4];
#pragma unroll
            for (int f = 0; f < 2; f++)
                ldsm_x4(af[f], aaddr[f] + c * 128 + ks * 32);
#pragma unroll
            for (int jj = 0; jj < 4; jj++) {
                uint32_t bf[4];
                ldsm_x4(bf, buf + bbase[jj] + ks * 32);
                mma_fp16(acc[0][2 * jj], af[0], bf[0], bf[1]);
                mma_fp16(acc[1][2 * jj], af[1], bf[0], bf[1]);
                mma_fp16(acc[0][2 * jj + 1], af[0], bf[2], bf[3]);
                mma_fp16(acc[1][2 * jj + 1], af[1], bf[2], bf[3]);
            }
        }
        __syncthreads();
    }

    float* stage = (float*)(smem + SB_OFF);
#pragma unroll
    for (int cg = 0; cg < 4; cg++) {
        if (wn == cg) {
#pragma unroll
            for (int f = 0; f < 2; f++)
#pragma unroll
                for (int j = 0; j < 8; j++)
#pragma unroll
                    for (int q = 0; q < 4; q++) {
                        int row = wm * 32 + f * 16 + g + 8 * (q >> 1);
                        int col = 8 * j + 2 * t + (q & 1);
                        stage[row * 65 + col] = acc[f][j][q];
                    }
        }
        __syncthreads();
#pragma unroll
        for (int i = 0; i < 16; i++) {
            int idx = tid + i * 512;
            int row = idx >> 6;
            int col = idx & 63;
            out[(size_t)row * VSZ + v0 + cg * 64 + col] =
                stage[row * 65 + col] + bout[v0 + cg * 64 + col];
        }
        __syncthreads();
    }
}

// ---------------- K8: in-place log_softmax over vocab (float4) -----------
__global__ __launch_bounds__(1024)
void logsoftmax_kernel(float* __restrict__ out) {
    const int b = blockIdx.x;
    const int tid = threadIdx.x;  // 1024
    __shared__ float red[1024];
    float4* row4 = (float4*)(out + (size_t)b * VSZ);  // 8000 float4

    float m = -1e30f;
    for (int v = tid; v < 8000; v += 1024) {
        float4 x = row4[v];
        m = fmaxf(m, fmaxf(fmaxf(x.x, x.y), fmaxf(x.z, x.w)));
    }
    red[tid] = m;
    __syncthreads();
    for (int d = 512; d > 0; d >>= 1) {
        if (tid < d) red[tid] = fmaxf(red[tid], red[tid + d]);
        __syncthreads();
    }
    m = red[0];
    __syncthreads();

    float s = 0.f;
    for (int v = tid; v < 8000; v += 1024) {
        float4 x = row4[v];
        s += expf(x.x - m) + expf(x.y - m) + expf(x.z - m) + expf(x.w - m);
    }
    red[tid] = s;
    __syncthreads();
    for (int d = 512; d > 0; d >>= 1) {
        if (tid < d) red[tid] += red[tid + d];
        __syncthreads();
    }
    float lse = m + logf(red[0]);
    for (int v = tid; v < 8000; v += 1024) {
        float4 x = row4[v];
        x.x -= lse; x.y -= lse; x.z -= lse; x.w -= lse;
        row4[v] = x;
    }
}

// ---------------- launch ----------------
extern "C" void kernel_launch(void* const* d_in, const int* in_sizes, int n_in,
                              void* d_out, int out_size) {
    const int* inp = (const int*)d_in[0];
    const float* hidden = (const float*)d_in[1];
    const float* enc = (const float*)d_in[2];
    const float* emb = (const float*)d_in[3];
    const float* W1 = (const float*)d_in[4];
    const float* W2 = (const float*)d_in[5];
    const float* W3 = (const float*)d_in[6];
    const float* b2 = (const float*)d_in[7];
    const float* b3 = (const float*)d_in[8];
    const float* V = (const float*)d_in[9];
    const float* Wih0 = (const float*)d_in[10];
    const float* Whh0 = (const float*)d_in[11];
    const float* bih0 = (const float*)d_in[12];
    const float* bhh0 = (const float*)d_in[13];
    const float* Wih1 = (const float*)d_in[14];
    const float* Whh1 = (const float*)d_in[15];
    const float* bih1 = (const float*)d_in[16];
    const float* bhh1 = (const float*)d_in[17];
    const float* Wout = (const float*)d_in[18];
    const float* bout = (const float*)d_in[19];

    float* out = (float*)d_out;
    float* hid_out = out + (size_t)Bd * VSZ;

    cudaFuncSetAttribute(scores_mma_kernel,
                         cudaFuncAttributeMaxDynamicSharedMemorySize, SC_SMEM);
    cudaFuncSetAttribute(logits_mma_kernel,
                         cudaFuncAttributeMaxDynamicSharedMemorySize, LG_SMEM);

    prep_w1_kernel<<<Hd, Hd>>>(W1);
    prep_wout_kernel<<<8000, 256>>>(Wout);
    w2h_kernel<<<Bd, 512>>>(hidden, W2, b2);
    scores_mma_kernel<<<Bd * 16, 512, SC_SMEM>>>(enc, V);
    post_kernel<<<Bd, 768>>>(inp, emb, W3, b3, hidden,
                             Wih0, Whh0, bih0, bhh0,
                             Wih1, Whh1, bih1, bhh1, hid_out);
    logits_mma_kernel<<<VSZ / 256, 512, LG_SMEM>>>(bout, out);
    logsoftmax_kernel<<<Bd, 1024>>>(out);
}

// round 10
// speedup vs baseline: 1.2547x; 1.0547x over previous
#include <cuda_runtime.h>
#include <cuda_fp16.h>
#include <cstdint>

#define Bd 128
#define Sd 2048
#define Hd 256
#define Ed 256
#define VSZ 32000
#define NCH 32                              // 64-row S-chunks per batch

// ---------------- scratch (device globals; no allocation) ----------------
__device__ float g_w2h[Bd * Hd];
__device__ float g_mz[2 * Bd * NCH];        // per (b,chunk): local max, local sum
__device__ float g_XaP[NCH * Bd * Hd];      // per-tile partial numerators
__device__ __align__(16) __half g_h1h[Bd * Hd];

#define PAD_E 72
#define CH_HALF_E (Hd * PAD_E)              // 18432 elems = 36864 B per chunk
__device__ __align__(16) __half g_W1p[4 * CH_HALF_E];
__device__ __align__(16) __half g_Woutp[4 * VSZ * PAD_E];

// ---------------- helpers ----------------
__device__ __forceinline__ float fast_tanh(float x) {
    float y;
    asm("tanh.approx.f32 %0, %1;" : "=f"(y) : "f"(x));
    return y;
}
__device__ __forceinline__ uint32_t smem_u32(const void* p) {
    uint32_t a;
    asm("{ .reg .u64 t; cvta.to.shared.u64 t, %1; cvt.u32.u64 %0, t; }"
        : "=r"(a) : "l"(p));
    return a;
}
__device__ __forceinline__ void cp16(uint32_t dst, const void* src) {
    asm volatile("cp.async.cg.shared.global [%0], [%1], 16;"
                 :: "r"(dst), "l"(src) : "memory");
}
__device__ __forceinline__ void cp_commit() {
    asm volatile("cp.async.commit_group;" ::: "memory");
}
template <int N>
__device__ __forceinline__ void cp_wait() {
    asm volatile("cp.async.wait_group %0;" :: "n"(N) : "memory");
}
__device__ __forceinline__ void mma_fp16(float* d, const uint32_t* a,
                                         uint32_t b0, uint32_t b1) {
    asm volatile(
        "mma.sync.aligned.m16n8k16.row.col.f32.f16.f16.f32 "
        "{%0,%1,%2,%3}, {%4,%5,%6,%7}, {%8,%9}, {%0,%1,%2,%3};"
        : "+f"(d[0]), "+f"(d[1]), "+f"(d[2]), "+f"(d[3])
        : "r"(a[0]), "r"(a[1]), "r"(a[2]), "r"(a[3]), "r"(b0), "r"(b1));
}
__device__ __forceinline__ void ldsm_x4(uint32_t* r, uint32_t addr) {
    asm volatile(
        "ldmatrix.sync.aligned.m8n8.x4.shared.b16 {%0,%1,%2,%3}, [%4];"
        : "=r"(r[0]), "=r"(r[1]), "=r"(r[2]), "=r"(r[3]) : "r"(addr));
}

// ---------------- P0: pack W1 (transpose + fp16, padded) ----------------
__global__ void prep_w1_kernel(const float* __restrict__ W1) {
    int n = blockIdx.x;
    int k = threadIdx.x;
    float x = W1[k * Hd + n];
    int c = k >> 6;
    int kk = k & 63;
    g_W1p[c * CH_HALF_E + n * PAD_E + kk] = __float2half_rn(x);
}

// ---------------- P1: pack Wout -> fp16, chunked + padded ----------------
__global__ void prep_wout_kernel(const float* __restrict__ Wout) {
    int idx4 = (blockIdx.x * 256 + threadIdx.x) * 4;
    int v = idx4 >> 8;
    int k = idx4 & 255;
    float4 x = *(const float4*)(Wout + (size_t)v * Hd + k);
    __half2 a = {__float2half_rn(x.x), __float2half_rn(x.y)};
    __half2 b = {__float2half_rn(x.z), __float2half_rn(x.w)};
    uint2 w;
    w.x = *(uint32_t*)&a;
    w.y = *(uint32_t*)&b;
    *(uint2*)&g_Woutp[(size_t)(k >> 6) * VSZ * PAD_E + (size_t)v * PAD_E + (k & 63)] = w;
}

// ---------------- K1: w2h = hidden[1] @ W2 + b2 ----------------
__global__ void w2h_kernel(const float* __restrict__ hidden,
                           const float* __restrict__ W2,
                           const float* __restrict__ b2) {
    int b = blockIdx.x;
    int tid = threadIdx.x;  // 512
    int k = tid & 255;
    int h = tid >> 8;
    __shared__ float sh[Hd];
    __shared__ float part[512];
    if (tid < Hd) sh[tid] = hidden[(Bd + b) * Hd + tid];
    __syncthreads();
    float acc = 0.f;
#pragma unroll 16
    for (int j = h * 128; j < h * 128 + 128; j++) acc += sh[j] * W2[j * Hd + k];
    part[tid] = acc;
    __syncthreads();
    if (tid < 256) g_w2h[b * Hd + tid] = part[tid] + part[tid + 256] + b2[tid];
}

// ---------------- K2: scores + local softmax + partial Xa numerator -------
// CTA: 64m x 256n, 8 warps (2m x 4n), 2 CTAs/SM. fp16 mma + ldmatrix.
// SMEM: A [64 x 528B] = 33792; B: 2 x 36864 at 33792.
#define SA_HI 0
#define SB_OFF 33792
#define SB_STRIDE 36864
#define SC_SMEM (33792 + 2 * 36864)
__global__ __launch_bounds__(256, 2)
void scores_mma_kernel(const float* __restrict__ enc,
                       const float* __restrict__ Vv) {
    extern __shared__ __align__(16) char smem[];
    const uint32_t sm_b = smem_u32(smem);
    const int tid = threadIdx.x;
    const int wid = tid >> 5;
    const int lane = tid & 31;
    const int g = lane >> 2;
    const int t = lane & 3;
    const int wm = wid >> 2;   // 0..1 (m group of 32)
    const int wn = wid & 3;    // 0..3 (n group of 64)
    const int quad = lane >> 3;
    const int r8 = lane & 7;
    const int b = blockIdx.x >> 5;
    const int chunk = blockIdx.x & (NCH - 1);
    const int m0 = blockIdx.x * 64;
    const float* encb = enc + (size_t)m0 * Hd;

    float acc[2][8][4];
#pragma unroll
    for (int f = 0; f < 2; f++)
#pragma unroll
        for (int j = 0; j < 8; j++)
#pragma unroll
            for (int q = 0; q < 4; q++) acc[f][j][q] = 0.f;

    uint32_t aaddr[2];
#pragma unroll
    for (int f = 0; f < 2; f++)
        aaddr[f] = sm_b + (wm * 32 + f * 16 + ((quad & 1) << 3) + r8) * 528
                 + ((quad >> 1) << 4);
    uint32_t bbase[4];
#pragma unroll
    for (int jj = 0; jj < 4; jj++)
        bbase[jj] = (wn * 64 + jj * 16 + ((quad >> 1) << 3) + r8) * 144
                  + ((quad & 1) << 4);

    // ---- issue B stage 0 (2304 x 16B) ----
    {
        const char* src = (const char*)g_W1p;
#pragma unroll
        for (int i = 0; i < 9; i++) {
            int idx = tid + i * 256;
            cp16(sm_b + SB_OFF + idx * 16, src + idx * 16);
        }
        cp_commit();
    }

    // ---- fill A (64 x 256 fp32 -> fp16), overlaps with cp.async ----
    {
#pragma unroll
        for (int i = 0; i < 32; i++) {
            int idx = tid + i * 256;        // 8192 float2
            int row = idx >> 7;
            int kp = idx & 127;
            float2 v = *(const float2*)(encb + (size_t)row * Hd + kp * 2);
            __half2 hp = {__float2half_rn(v.x), __float2half_rn(v.y)};
            *(uint32_t*)(smem + SA_HI + row * 528 + kp * 4) = *(uint32_t*)&hp;
        }
    }

    // ---- 4 pipelined B stages ----
#pragma unroll
    for (int c = 0; c < 4; c++) {
        if (c < 3) {
            const char* src = (const char*)(g_W1p + (size_t)(c + 1) * CH_HALF_E);
            uint32_t dst = sm_b + SB_OFF + ((c + 1) & 1) * SB_STRIDE;
#pragma unroll
            for (int i = 0; i < 9; i++) {
                int idx = tid + i * 256;
                cp16(dst + idx * 16, src + idx * 16);
            }
            cp_commit();
            cp_wait<1>();
        } else {
            cp_wait<0>();
        }
        __syncthreads();

        const uint32_t buf = sm_b + SB_OFF + (c & 1) * SB_STRIDE;
#pragma unroll
        for (int ks = 0; ks < 4; ks++) {
            uint32_t af[2][4];
#pragma unroll
            for (int f = 0; f < 2; f++)
                ldsm_x4(af[f], aaddr[f] + c * 128 + ks * 32);
#pragma unroll
            for (int jj = 0; jj < 4; jj++) {
                uint32_t bf[4];
                ldsm_x4(bf, buf + bbase[jj] + ks * 32);
                mma_fp16(acc[0][2 * jj], af[0], bf[0], bf[1]);
                mma_fp16(acc[1][2 * jj], af[1], bf[0], bf[1]);
                mma_fp16(acc[0][2 * jj + 1], af[0], bf[2], bf[3]);
                mma_fp16(acc[1][2 * jj + 1], af[1], bf[2], bf[3]);
            }
        }
        __syncthreads();
    }

    // ---- epilogue: scores -> local softmax -> partial numerator ----
    float* EP = (float*)(smem + SB_OFF);
    float* sw2 = EP;            // 256
    float* sV = EP + 256;       // 256
    float* sp = EP + 512;       // 256 (4 n-groups x 64 rows)
    float* red = EP + 768;      // 64
    float* e_arr = EP + 832;    // 64
    sw2[tid] = g_w2h[b * Hd + tid];
    sV[tid] = Vv[tid];
    __syncthreads();

    float p[2][2] = {{0.f, 0.f}, {0.f, 0.f}};
#pragma unroll
    for (int f = 0; f < 2; f++)
#pragma unroll
        for (int j = 0; j < 8; j++) {
            int cc = wn * 64 + 8 * j + 2 * t;
            float v0 = sV[cc], v1 = sV[cc + 1];
            float w0 = sw2[cc], w1 = sw2[cc + 1];
            p[f][0] += v0 * fast_tanh(acc[f][j][0] + w0)
                     + v1 * fast_tanh(acc[f][j][1] + w1);
            p[f][1] += v0 * fast_tanh(acc[f][j][2] + w0)
                     + v1 * fast_tanh(acc[f][j][3] + w1);
        }
#pragma unroll
    for (int f = 0; f < 2; f++)
#pragma unroll
        for (int u = 0; u < 2; u++) {
            float v = p[f][u];
            v += __shfl_xor_sync(0xffffffffu, v, 1);
            v += __shfl_xor_sync(0xffffffffu, v, 2);
            if (t == 0) {
                int r = wm * 32 + f * 16 + g + 8 * u;
                sp[wn * 64 + r] = v;
            }
        }
    __syncthreads();

    float sc = 0.f;
    if (tid < 64) {
        sc = sp[tid] + sp[64 + tid] + sp[128 + tid] + sp[192 + tid];
        red[tid] = sc;
    }
    __syncthreads();
    for (int d = 32; d > 0; d >>= 1) {
        if (tid < d) red[tid] = fmaxf(red[tid], red[tid + d]);
        __syncthreads();
    }
    float mloc = red[0];
    __syncthreads();
    if (tid < 64) {
        float e = expf(sc - mloc);
        e_arr[tid] = e;
        red[tid] = e;
    }
    __syncthreads();
    for (int d = 32; d > 0; d >>= 1) {
        if (tid < d) red[tid] += red[tid + d];
        __syncthreads();
    }
    if (tid == 0) {
        g_mz[2 * blockIdx.x] = mloc;
        g_mz[2 * blockIdx.x + 1] = red[0];
    }
    __syncthreads();

    // partial numerator: one thread per h, sum over the 64 tile rows
    float a2 = 0.f;
#pragma unroll 8
    for (int s = 0; s < 64; s++) {
        __half hv = *(const __half*)(smem + SA_HI + s * 528 + tid * 2);
        a2 += e_arr[s] * __half2float(hv);
    }
    g_XaP[((size_t)chunk * Bd + b) * Hd + tid] = a2;
}

// ---------------- K4: fused Xa-combine + res + GRU0 + GRU1 (per-b) -------
__global__ __launch_bounds__(768)
void post_kernel(const int* __restrict__ inp,
                 const float* __restrict__ emb,
                 const float* __restrict__ W3,
                 const float* __restrict__ b3,
                 const float* __restrict__ hidden,
                 const float* __restrict__ Wih0,
                 const float* __restrict__ Whh0,
                 const float* __restrict__ bih0,
                 const float* __restrict__ bhh0,
                 const float* __restrict__ Wih1,
                 const float* __restrict__ Whh1,
                 const float* __restrict__ bih1,
                 const float* __restrict__ bhh1,
                 float* __restrict__ hid_out) {
    const int b = blockIdx.x;
    const int tid = threadIdx.x;  // 768
    __shared__ float cat[Ed + Hd];
    __shared__ float part[512];
    __shared__ float sgi[768], sgh[768];
    __shared__ float sx[Hd], sh[Hd];

    int token = inp[b];
    if (tid < Ed) {
        cat[tid] = emb[(size_t)token * Ed + tid];
    } else if (tid < Ed + Hd) {
        int hh = tid - Ed;
        float M = -1e30f;
#pragma unroll
        for (int i = 0; i < NCH; i++)
            M = fmaxf(M, g_mz[2 * (b * NCH + i)]);
        float Z = 0.f, X = 0.f;
#pragma unroll
        for (int i = 0; i < NCH; i++) {
            float w = expf(g_mz[2 * (b * NCH + i)] - M);
            Z += w * g_mz[2 * (b * NCH + i) + 1];
            X += w * g_XaP[((size_t)i * Bd + b) * Hd + hh];
        }
        cat[tid] = X / Z;
    }
    __syncthreads();
    if (tid < 512) {
        int k = tid & 255;
        int h = tid >> 8;
        float acc = 0.f;
#pragma unroll 16
        for (int j = h * 256; j < h * 256 + 256; j++)
            acc += cat[j] * W3[j * Hd + k];
        part[tid] = acc;
    }
    __syncthreads();
    if (tid < 256) {
        sx[tid] = part[tid] + part[tid + 256] + b3[tid];
        sh[tid] = hidden[b * Hd + tid];
    }
    __syncthreads();

#pragma unroll
    for (int cell = 0; cell < 2; cell++) {
        const float* Wih = cell ? Wih1 : Wih0;
        const float* Whh = cell ? Whh1 : Whh0;
        const float* bih = cell ? bih1 : bih0;
        const float* bhh = cell ? bhh1 : bhh0;
        {
            int gidx = tid;
            const float4* wi = (const float4*)(Wih + (size_t)gidx * Hd);
            const float4* wh = (const float4*)(Whh + (size_t)gidx * Hd);
            float gi = bih[gidx], gh = bhh[gidx];
#pragma unroll 16
            for (int q = 0; q < Hd / 4; q++) {
                float4 a = wi[q];
                float4 c = wh[q];
                float4 xv = *(const float4*)&sx[q * 4];
                float4 hv = *(const float4*)&sh[q * 4];
                gi += a.x * xv.x + a.y * xv.y + a.z * xv.z + a.w * xv.w;
                gh += c.x * hv.x + c.y * hv.y + c.z * hv.z + c.w * hv.w;
            }
            sgi[gidx] = gi;
            sgh[gidx] = gh;
        }
        __syncthreads();
        if (tid < 256) {
            int j = tid;
            float r = 1.f / (1.f + expf(-(sgi[j] + sgh[j])));
            float z = 1.f / (1.f + expf(-(sgi[Hd + j] + sgh[Hd + j])));
            float n = tanhf(sgi[2 * Hd + j] + r * sgh[2 * Hd + j]);
            float hn = (1.f - z) * n + z * sh[j];
            hid_out[((size_t)cell * Bd + b) * Hd + j] = hn;
            if (cell == 0) {
                part[j] = hn;
            } else {
                g_h1h[b * Hd + j] = __float2half_rn(hn);
            }
        }
        __syncthreads();
        if (cell == 0 && tid < 256) {
            sx[tid] = part[tid];
            sh[tid] = hidden[(Bd + b) * Hd + tid];
        }
        __syncthreads();
    }
}

// ---------------- K7: logits via fp16 mma + ldmatrix ----------------
#define LSA 0
#define LSB_OFF 67584
#define LG_SMEM (67584 + 2 * 36864)
__global__ __launch_bounds__(512, 1)
void logits_mma_kernel(const float* __restrict__ bout,
                       float* __restrict__ out) {
    extern __shared__ __align__(16) char smem[];
    const uint32_t sm_b = smem_u32(smem);
    const int tid = threadIdx.x;
    const int wid = tid >> 5;
    const int lane = tid & 31;
    const int g = lane >> 2;
    const int t = lane & 3;
    const int wm = wid >> 2;
    const int wn = wid & 3;
    const int quad = lane >> 3;
    const int r8 = lane & 7;
    const int v0 = blockIdx.x * 256;

    float acc[2][8][4];
#pragma unroll
    for (int f = 0; f < 2; f++)
#pragma unroll
        for (int j = 0; j < 8; j++)
#pragma unroll
            for (int q = 0; q < 4; q++) acc[f][j][q] = 0.f;

    uint32_t aaddr[2];
#pragma unroll
    for (int f = 0; f < 2; f++)
        aaddr[f] = sm_b + (wm * 32 + f * 16 + ((quad & 1) << 3) + r8) * 528
                 + ((quad >> 1) << 4);
    uint32_t bbase[4];
#pragma unroll
    for (int jj = 0; jj < 4; jj++)
        bbase[jj] = (wn * 64 + jj * 16 + ((quad >> 1) << 3) + r8) * 144
                  + ((quad & 1) << 4);

    {
        const char* src = (const char*)(g_Woutp + (size_t)v0 * PAD_E);
#pragma unroll
        for (int i = 0; i < 5; i++) {
            int idx = tid + i * 512;
            if (idx < 2304) cp16(sm_b + LSB_OFF + idx * 16, src + idx * 16);
        }
        cp_commit();
    }
    {
        const uint32_t* src = (const uint32_t*)g_h1h;
#pragma unroll
        for (int i = 0; i < 32; i++) {
            int idx = tid + i * 512;
            int row = idx >> 7;
            int c32 = idx & 127;
            *(uint32_t*)(smem + row * 528 + c32 * 4) = src[idx];
        }
    }

#pragma unroll
    for (int c = 0; c < 4; c++) {
        if (c < 3) {
            const char* src =
                (const char*)(g_Woutp + ((size_t)(c + 1) * VSZ + v0) * PAD_E);
            uint32_t dst = sm_b + LSB_OFF + ((c + 1) & 1) * SB_STRIDE;
#pragma unroll
            for (int i = 0; i < 5; i++) {
                int idx = tid + i * 512;
                if (idx < 2304) cp16(dst + idx * 16, src + idx * 16);
            }
            cp_commit();
            cp_wait<1>();
        } else {
            cp_wait<0>();
        }
        __syncthreads();

        const uint32_t buf = sm_b + LSB_OFF + (c & 1) * SB_STRIDE;
#pragma unroll
        for (int ks = 0; ks < 4; ks++) {
            uint32_t af[2][4];
#pragma unroll
            for (int f = 0; f < 2; f++)
                ldsm_x4(af[f], aaddr[f] + c * 128 + ks * 32);
#pragma unroll
            for (int jj = 0; jj < 4; jj++) {
                uint32_t bf[4];
                ldsm_x4(bf, buf + bbase[jj] + ks * 32);
                mma_fp16(acc[0][2 * jj], af[0], bf[0], bf[1]);
                mma_fp16(acc[1][2 * jj], af[1], bf[0], bf[1]);
                mma_fp16(acc[0][2 * jj + 1], af[0], bf[2], bf[3]);
                mma_fp16(acc[1][2 * jj + 1], af[1], bf[2], bf[3]);
            }
        }
        __syncthreads();
    }

    float* stage = (float*)(smem + LSB_OFF);
#pragma unroll
    for (int cg = 0; cg < 4; cg++) {
        if (wn == cg) {
#pragma unroll
            for (int f = 0; f < 2; f++)
#pragma unroll
                for (int j = 0; j < 8; j++)
#pragma unroll
                    for (int q = 0; q < 4; q++) {
                        int row = wm * 32 + f * 16 + g + 8 * (q >> 1);
                        int col = 8 * j + 2 * t + (q & 1);
                        stage[row * 65 + col] = acc[f][j][q];
                    }
        }
        __syncthreads();
#pragma unroll
        for (int i = 0; i < 16; i++) {
            int idx = tid + i * 512;
            int row = idx >> 6;
            int col = idx & 63;
            out[(size_t)row * VSZ + v0 + cg * 64 + col] =
                stage[row * 65 + col] + bout[v0 + cg * 64 + col];
        }
        __syncthreads();
    }
}

// ---------------- K8: in-place log_softmax over vocab (float4) -----------
__global__ __launch_bounds__(1024)
void logsoftmax_kernel(float* __restrict__ out) {
    const int b = blockIdx.x;
    const int tid = threadIdx.x;  // 1024
    __shared__ float red[1024];
    float4* row4 = (float4*)(out + (size_t)b * VSZ);  // 8000 float4

    float m = -1e30f;
    for (int v = tid; v < 8000; v += 1024) {
        float4 x = row4[v];
        m = fmaxf(m, fmaxf(fmaxf(x.x, x.y), fmaxf(x.z, x.w)));
    }
    red[tid] = m;
    __syncthreads();
    for (int d = 512; d > 0; d >>= 1) {
        if (tid < d) red[tid] = fmaxf(red[tid], red[tid + d]);
        __syncthreads();
    }
    m = red[0];
    __syncthreads();

    float s = 0.f;
    for (int v = tid; v < 8000; v += 1024) {
        float4 x = row4[v];
        s += expf(x.x - m) + expf(x.y - m) + expf(x.z - m) + expf(x.w - m);
    }
    red[tid] = s;
    __syncthreads();
    for (int d = 512; d > 0; d >>= 1) {
        if (tid < d) red[tid] += red[tid + d];
        __syncthreads();
    }
    float lse = m + logf(red[0]);
    for (int v = tid; v < 8000; v += 1024) {
        float4 x = row4[v];
        x.x -= lse; x.y -= lse; x.z -= lse; x.w -= lse;
        row4[v] = x;
    }
}

// ---------------- launch ----------------
extern "C" void kernel_launch(void* const* d_in, const int* in_sizes, int n_in,
                              void* d_out, int out_size) {
    const int* inp = (const int*)d_in[0];
    const float* hidden = (const float*)d_in[1];
    const float* enc = (const float*)d_in[2];
    const float* emb = (const float*)d_in[3];
    const float* W1 = (const float*)d_in[4];
    const float* W2 = (const float*)d_in[5];
    const float* W3 = (const float*)d_in[6];
    const float* b2 = (const float*)d_in[7];
    const float* b3 = (const float*)d_in[8];
    const float* V = (const float*)d_in[9];
    const float* Wih0 = (const float*)d_in[10];
    const float* Whh0 = (const float*)d_in[11];
    const float* bih0 = (const float*)d_in[12];
    const float* bhh0 = (const float*)d_in[13];
    const float* Wih1 = (const float*)d_in[14];
    const float* Whh1 = (const float*)d_in[15];
    const float* bih1 = (const float*)d_in[16];
    const float* bhh1 = (const float*)d_in[17];
    const float* Wout = (const float*)d_in[18];
    const float* bout = (const float*)d_in[19];

    float* out = (float*)d_out;
    float* hid_out = out + (size_t)Bd * VSZ;

    cudaFuncSetAttribute(scores_mma_kernel,
                         cudaFuncAttributeMaxDynamicSharedMemorySize, SC_SMEM);
    cudaFuncSetAttribute(logits_mma_kernel,
                         cudaFuncAttributeMaxDynamicSharedMemorySize, LG_SMEM);

    prep_w1_kernel<<<Hd, Hd>>>(W1);
    prep_wout_kernel<<<8000, 256>>>(Wout);
    w2h_kernel<<<Bd, 512>>>(hidden, W2, b2);
    scores_mma_kernel<<<Bd * NCH, 256, SC_SMEM>>>(enc, V);
    post_kernel<<<Bd, 768>>>(inp, emb, W3, b3, hidden,
                             Wih0, Whh0, bih0, bhh0,
                             Wih1, Whh1, bih1, bhh1, hid_out);
    logits_mma_kernel<<<VSZ / 256, 512, LG_SMEM>>>(bout, out);
    logsoftmax_kernel<<<Bd, 1024>>>(out);
}

// round 11
// speedup vs baseline: 1.2633x; 1.0068x over previous
#include <cuda_runtime.h>
#include <cuda_fp16.h>
#include <cstdint>

#define Bd 128
#define Sd 2048
#define Hd 256
#define Ed 256
#define VSZ 32000
#define NCH 32                              // 64-row S-chunks per batch
#define NVB 125                             // vocab blocks of 256

// ---------------- scratch (device globals; no allocation) ----------------
__device__ float g_w2h[Bd * Hd];
__device__ float g_mz[2 * Bd * NCH];        // per (b,chunk): local max, local sum
__device__ float g_XaP[NCH * Bd * Hd];      // per-tile partial numerators
__device__ float g_cat[Bd * 512];
__device__ float g_res[Bd * Hd];
__device__ float g_x1[Bd * Hd];             // h0 (input to cell 1)
__device__ float g_gi[Bd * 768];
__device__ float g_gh[Bd * 768];
__device__ float g_lmz[Bd * NVB * 2];       // logits per-(b,vblock) max/sumexp
__device__ __align__(16) __half g_h1h[Bd * Hd];

#define PAD_E 72
#define CH_HALF_E (Hd * PAD_E)              // 18432 elems = 36864 B per chunk
__device__ __align__(16) __half g_W1p[4 * CH_HALF_E];
__device__ __align__(16) __half g_Woutp[4 * VSZ * PAD_E];

// ---------------- helpers ----------------
__device__ __forceinline__ float fast_tanh(float x) {
    float y;
    asm("tanh.approx.f32 %0, %1;" : "=f"(y) : "f"(x));
    return y;
}
__device__ __forceinline__ uint32_t smem_u32(const void* p) {
    uint32_t a;
    asm("{ .reg .u64 t; cvta.to.shared.u64 t, %1; cvt.u32.u64 %0, t; }"
        : "=r"(a) : "l"(p));
    return a;
}
__device__ __forceinline__ void cp16(uint32_t dst, const void* src) {
    asm volatile("cp.async.cg.shared.global [%0], [%1], 16;"
                 :: "r"(dst), "l"(src) : "memory");
}
__device__ __forceinline__ void cp_commit() {
    asm volatile("cp.async.commit_group;" ::: "memory");
}
template <int N>
__device__ __forceinline__ void cp_wait() {
    asm volatile("cp.async.wait_group %0;" :: "n"(N) : "memory");
}
__device__ __forceinline__ void mma_fp16(float* d, const uint32_t* a,
                                         uint32_t b0, uint32_t b1) {
    asm volatile(
        "mma.sync.aligned.m16n8k16.row.col.f32.f16.f16.f32 "
        "{%0,%1,%2,%3}, {%4,%5,%6,%7}, {%8,%9}, {%0,%1,%2,%3};"
        : "+f"(d[0]), "+f"(d[1]), "+f"(d[2]), "+f"(d[3])
        : "r"(a[0]), "r"(a[1]), "r"(a[2]), "r"(a[3]), "r"(b0), "r"(b1));
}
__device__ __forceinline__ void ldsm_x4(uint32_t* r, uint32_t addr) {
    asm volatile(
        "ldmatrix.sync.aligned.m8n8.x4.shared.b16 {%0,%1,%2,%3}, [%4];"
        : "=r"(r[0]), "=r"(r[1]), "=r"(r[2]), "=r"(r[3]) : "r"(addr));
}

// ---------------- P0: pack W1 (transpose + fp16, padded) ----------------
__global__ void prep_w1_kernel(const float* __restrict__ W1) {
    int n = blockIdx.x;
    int k = threadIdx.x;
    float x = W1[k * Hd + n];
    int c = k >> 6;
    int kk = k & 63;
    g_W1p[c * CH_HALF_E + n * PAD_E + kk] = __float2half_rn(x);
}

// ---------------- P1: pack Wout -> fp16, chunked + padded ----------------
__global__ void prep_wout_kernel(const float* __restrict__ Wout) {
    int idx4 = (blockIdx.x * 256 + threadIdx.x) * 4;
    int v = idx4 >> 8;
    int k = idx4 & 255;
    float4 x = *(const float4*)(Wout + (size_t)v * Hd + k);
    __half2 a = {__float2half_rn(x.x), __float2half_rn(x.y)};
    __half2 b = {__float2half_rn(x.z), __float2half_rn(x.w)};
    uint2 w;
    w.x = *(uint32_t*)&a;
    w.y = *(uint32_t*)&b;
    *(uint2*)&g_Woutp[(size_t)(k >> 6) * VSZ * PAD_E + (size_t)v * PAD_E + (k & 63)] = w;
}

// ---------------- K1: w2h = hidden[1] @ W2 + b2 ----------------
__global__ void w2h_kernel(const float* __restrict__ hidden,
                           const float* __restrict__ W2,
                           const float* __restrict__ b2) {
    int b = blockIdx.x;
    int tid = threadIdx.x;  // 512
    int k = tid & 255;
    int h = tid >> 8;
    __shared__ float sh[Hd];
    __shared__ float part[512];
    if (tid < Hd) sh[tid] = hidden[(Bd + b) * Hd + tid];
    __syncthreads();
    float acc = 0.f;
#pragma unroll 16
    for (int j = h * 128; j < h * 128 + 128; j++) acc += sh[j] * W2[j * Hd + k];
    part[tid] = acc;
    __syncthreads();
    if (tid < 256) g_w2h[b * Hd + tid] = part[tid] + part[tid + 256] + b2[tid];
}

// ---------------- K2: scores + local softmax + partial Xa numerator -------
// CTA: 64m x 256n, 8 warps (2m x 4n), 2 CTAs/SM. fp16 mma + ldmatrix.
#define SA_HI 0
#define SB_OFF 33792
#define SB_STRIDE 36864
#define SC_SMEM (33792 + 2 * 36864)
__global__ __launch_bounds__(256, 2)
void scores_mma_kernel(const float* __restrict__ enc,
                       const float* __restrict__ Vv) {
    extern __shared__ __align__(16) char smem[];
    const uint32_t sm_b = smem_u32(smem);
    const int tid = threadIdx.x;
    const int wid = tid >> 5;
    const int lane = tid & 31;
    const int g = lane >> 2;
    const int t = lane & 3;
    const int wm = wid >> 2;
    const int wn = wid & 3;
    const int quad = lane >> 3;
    const int r8 = lane & 7;
    const int b = blockIdx.x >> 5;
    const int chunk = blockIdx.x & (NCH - 1);
    const int m0 = blockIdx.x * 64;
    const float* encb = enc + (size_t)m0 * Hd;

    float acc[2][8][4];
#pragma unroll
    for (int f = 0; f < 2; f++)
#pragma unroll
        for (int j = 0; j < 8; j++)
#pragma unroll
            for (int q = 0; q < 4; q++) acc[f][j][q] = 0.f;

    uint32_t aaddr[2];
#pragma unroll
    for (int f = 0; f < 2; f++)
        aaddr[f] = sm_b + (wm * 32 + f * 16 + ((quad & 1) << 3) + r8) * 528
                 + ((quad >> 1) << 4);
    uint32_t bbase[4];
#pragma unroll
    for (int jj = 0; jj < 4; jj++)
        bbase[jj] = (wn * 64 + jj * 16 + ((quad >> 1) << 3) + r8) * 144
                  + ((quad & 1) << 4);

    // ---- issue B stage 0 (2304 x 16B) ----
    {
        const char* src = (const char*)g_W1p;
#pragma unroll
        for (int i = 0; i < 9; i++) {
            int idx = tid + i * 256;
            cp16(sm_b + SB_OFF + idx * 16, src + idx * 16);
        }
        cp_commit();
    }

    // ---- fill A (64 x 256 fp32 -> fp16) via float4, overlaps cp.async ----
    {
#pragma unroll
        for (int i = 0; i < 16; i++) {
            int idx = tid + i * 256;        // 4096 float4
            int row = idx >> 6;
            int kp = idx & 63;
            float4 v = *(const float4*)(encb + (size_t)row * Hd + kp * 4);
            __half2 h0 = {__float2half_rn(v.x), __float2half_rn(v.y)};
            __half2 h1 = {__float2half_rn(v.z), __float2half_rn(v.w)};
            uint2 w;
            w.x = *(uint32_t*)&h0;
            w.y = *(uint32_t*)&h1;
            *(uint2*)(smem + SA_HI + row * 528 + kp * 8) = w;
        }
    }

    // ---- 4 pipelined B stages ----
#pragma unroll
    for (int c = 0; c < 4; c++) {
        if (c < 3) {
            const char* src = (const char*)(g_W1p + (size_t)(c + 1) * CH_HALF_E);
            uint32_t dst = sm_b + SB_OFF + ((c + 1) & 1) * SB_STRIDE;
#pragma unroll
            for (int i = 0; i < 9; i++) {
                int idx = tid + i * 256;
                cp16(dst + idx * 16, src + idx * 16);
            }
            cp_commit();
            cp_wait<1>();
        } else {
            cp_wait<0>();
        }
        __syncthreads();

        const uint32_t buf = sm_b + SB_OFF + (c & 1) * SB_STRIDE;
#pragma unroll
        for (int ks = 0; ks < 4; ks++) {
            uint32_t af[2][4];
#pragma unroll
            for (int f = 0; f < 2; f++)
                ldsm_x4(af[f], aaddr[f] + c * 128 + ks * 32);
#pragma unroll
            for (int jj = 0; jj < 4; jj++) {
                uint32_t bf[4];
                ldsm_x4(bf, buf + bbase[jj] + ks * 32);
                mma_fp16(acc[0][2 * jj], af[0], bf[0], bf[1]);
                mma_fp16(acc[1][2 * jj], af[1], bf[0], bf[1]);
                mma_fp16(acc[0][2 * jj + 1], af[0], bf[2], bf[3]);
                mma_fp16(acc[1][2 * jj + 1], af[1], bf[2], bf[3]);
            }
        }
        __syncthreads();
    }

    // ---- epilogue: scores -> local softmax -> partial numerator ----
    float* EP = (float*)(smem + SB_OFF);
    float* sw2 = EP;            // 256
    float* sV = EP + 256;       // 256
    float* sp = EP + 512;       // 256
    float* red = EP + 768;      // 64
    float* e_arr = EP + 832;    // 64
    sw2[tid] = g_w2h[b * Hd + tid];
    sV[tid] = Vv[tid];
    __syncthreads();

    float p[2][2] = {{0.f, 0.f}, {0.f, 0.f}};
#pragma unroll
    for (int f = 0; f < 2; f++)
#pragma unroll
        for (int j = 0; j < 8; j++) {
            int cc = wn * 64 + 8 * j + 2 * t;
            float v0 = sV[cc], v1 = sV[cc + 1];
            float w0 = sw2[cc], w1 = sw2[cc + 1];
            p[f][0] += v0 * fast_tanh(acc[f][j][0] + w0)
                     + v1 * fast_tanh(acc[f][j][1] + w1);
            p[f][1] += v0 * fast_tanh(acc[f][j][2] + w0)
                     + v1 * fast_tanh(acc[f][j][3] + w1);
        }
#pragma unroll
    for (int f = 0; f < 2; f++)
#pragma unroll
        for (int u = 0; u < 2; u++) {
            float v = p[f][u];
            v += __shfl_xor_sync(0xffffffffu, v, 1);
            v += __shfl_xor_sync(0xffffffffu, v, 2);
            if (t == 0) {
                int r = wm * 32 + f * 16 + g + 8 * u;
                sp[wn * 64 + r] = v;
            }
        }
    __syncthreads();

    float sc = 0.f;
    if (tid < 64) {
        sc = sp[tid] + sp[64 + tid] + sp[128 + tid] + sp[192 + tid];
        red[tid] = sc;
    }
    __syncthreads();
    for (int d = 32; d > 0; d >>= 1) {
        if (tid < d) red[tid] = fmaxf(red[tid], red[tid + d]);
        __syncthreads();
    }
    float mloc = red[0];
    __syncthreads();
    if (tid < 64) {
        float e = expf(sc - mloc);
        e_arr[tid] = e;
        red[tid] = e;
    }
    __syncthreads();
    for (int d = 32; d > 0; d >>= 1) {
        if (tid < d) red[tid] += red[tid + d];
        __syncthreads();
    }
    if (tid == 0) {
        g_mz[2 * blockIdx.x] = mloc;
        g_mz[2 * blockIdx.x + 1] = red[0];
    }
    __syncthreads();

    float a2 = 0.f;
#pragma unroll 8
    for (int s = 0; s < 64; s++) {
        __half hv = *(const __half*)(smem + SA_HI + s * 528 + tid * 2);
        a2 += e_arr[s] * __half2float(hv);
    }
    g_XaP[((size_t)chunk * Bd + b) * Hd + tid] = a2;
}

// ---------------- K3: cat = [emb[inp]; Xa-combined] ----------------
__global__ void cat_kernel(const int* __restrict__ inp,
                           const float* __restrict__ emb) {
    const int b = blockIdx.x;
    const int tid = threadIdx.x;  // 256
    int token = inp[b];
    g_cat[b * 512 + tid] = emb[(size_t)token * Ed + tid];
    float M = -1e30f;
#pragma unroll
    for (int i = 0; i < NCH; i++)
        M = fmaxf(M, g_mz[2 * (b * NCH + i)]);
    float Z = 0.f, X = 0.f;
#pragma unroll
    for (int i = 0; i < NCH; i++) {
        float w = expf(g_mz[2 * (b * NCH + i)] - M);
        Z += w * g_mz[2 * (b * NCH + i) + 1];
        X += w * g_XaP[((size_t)i * Bd + b) * Hd + tid];
    }
    g_cat[b * 512 + 256 + tid] = X / Z;
}

// ---------------- K4: res = cat @ W3 + b3 (16 n-slice CTAs) ---------------
// smem: w3t[16][524] (transposed slice) + cs[32][520] (cat b-tile)
#define RES_SMEM ((16 * 524 + 32 * 520) * 4)
__global__ __launch_bounds__(512)
void res_kernel(const float* __restrict__ W3, const float* __restrict__ b3) {
    extern __shared__ float rsm[];
    float* w3t = rsm;                // 16 x 524
    float* cs = rsm + 16 * 524;      // 32 x 520
    const int n0 = blockIdx.x * 16;
    const int tid = threadIdx.x;
    const int nn = tid & 15;
    const int bq = tid >> 4;         // 0..31

    for (int idx = tid; idx < 512 * 16; idx += 512) {
        int k = idx >> 4;
        int n = idx & 15;
        w3t[n * 524 + k] = W3[(size_t)k * Hd + n0 + n];
    }
    __syncthreads();

    for (int bt = 0; bt < 4; bt++) {
        for (int idx = tid; idx < 32 * 512; idx += 512) {
            int bb = idx >> 9;
            int k = idx & 511;
            cs[bb * 520 + k] = g_cat[(size_t)(bt * 32 + bb) * 512 + k];
        }
        __syncthreads();
        float acc = 0.f;
#pragma unroll 8
        for (int k4 = 0; k4 < 128; k4++) {
            float4 cv = *(const float4*)&cs[bq * 520 + k4 * 4];
            float4 wv = *(const float4*)&w3t[nn * 524 + k4 * 4];
            acc += cv.x * wv.x + cv.y * wv.y + cv.z * wv.z + cv.w * wv.w;
        }
        g_res[(size_t)(bt * 32 + bq) * Hd + n0 + nn] = acc + b3[n0 + nn];
        __syncthreads();
    }
}

// ---------------- K5: GRU gate GEMVs (grid 12 n-slices x 8 b-groups) ------
__global__ __launch_bounds__(512)
void gru_gates_kernel(const float* __restrict__ x,
                      const float* __restrict__ hprev,
                      const float* __restrict__ Wih,
                      const float* __restrict__ Whh,
                      const float* __restrict__ bih,
                      const float* __restrict__ bhh) {
    const int n0 = blockIdx.x * 64;
    const int b0 = blockIdx.y * 16;
    const int tid = threadIdx.x;
    __shared__ float xs[16][260], hs[16][260];
    for (int i = tid; i < 16 * 256; i += 512) {
        int bb = i >> 8;
        int k = i & 255;
        xs[bb][k] = x[(size_t)(b0 + bb) * Hd + k];
        hs[bb][k] = hprev[(size_t)(b0 + bb) * Hd + k];
    }
    __syncthreads();
    const int bb = tid & 15;
    const int g2 = tid >> 4;  // 0..31
#pragma unroll
    for (int gg = 0; gg < 2; gg++) {
        int gr = n0 + g2 + gg * 32;
        const float4* wi = (const float4*)(Wih + (size_t)gr * Hd);
        const float4* wh = (const float4*)(Whh + (size_t)gr * Hd);
        float gi = bih[gr], gh = bhh[gr];
#pragma unroll 8
        for (int k4 = 0; k4 < 64; k4++) {
            float4 a = wi[k4];
            float4 c = wh[k4];
            float4 xv = *(const float4*)&xs[bb][k4 * 4];
            float4 hv = *(const float4*)&hs[bb][k4 * 4];
            gi += a.x * xv.x + a.y * xv.y + a.z * xv.z + a.w * xv.w;
            gh += c.x * hv.x + c.y * hv.y + c.z * hv.z + c.w * hv.w;
        }
        g_gi[(size_t)(b0 + bb) * 768 + gr] = gi;
        g_gh[(size_t)(b0 + bb) * 768 + gr] = gh;
    }
}

// ---------------- K6: GRU combine (elementwise) ----------------
__global__ void gru_combine_kernel(const float* __restrict__ hprev,
                                   int cell,
                                   float* __restrict__ hid_out) {
    int idx = blockIdx.x * 512 + threadIdx.x;  // 32768
    int b = idx >> 8;
    int j = idx & 255;
    float gir = g_gi[(size_t)b * 768 + j];
    float ghr = g_gh[(size_t)b * 768 + j];
    float giz = g_gi[(size_t)b * 768 + 256 + j];
    float ghz = g_gh[(size_t)b * 768 + 256 + j];
    float gin = g_gi[(size_t)b * 768 + 512 + j];
    float ghn = g_gh[(size_t)b * 768 + 512 + j];
    float r = 1.f / (1.f + expf(-(gir + ghr)));
    float z = 1.f / (1.f + expf(-(giz + ghz)));
    float n = tanhf(gin + r * ghn);
    float h = hprev[(size_t)b * Hd + j];
    float hn = (1.f - z) * n + z * h;
    hid_out[((size_t)cell * Bd + b) * Hd + j] = hn;
    if (cell == 0) g_x1[(size_t)b * Hd + j] = hn;
    else g_h1h[(size_t)b * Hd + j] = __float2half_rn(hn);
}

// ---------------- K7: logits via fp16 mma + ldmatrix + softmax partials ---
#define LSB_OFF 67584
#define LG_SMEM (67584 + 2 * 36864)
__global__ __launch_bounds__(512, 1)
void logits_mma_kernel(const float* __restrict__ bout,
                       float* __restrict__ out) {
    extern __shared__ __align__(16) char smem[];
    const uint32_t sm_b = smem_u32(smem);
    const int tid = threadIdx.x;
    const int wid = tid >> 5;
    const int lane = tid & 31;
    const int g = lane >> 2;
    const int t = lane & 3;
    const int wm = wid >> 2;
    const int wn = wid & 3;
    const int quad = lane >> 3;
    const int r8 = lane & 7;
    const int v0 = blockIdx.x * 256;

    float acc[2][8][4];
#pragma unroll
    for (int f = 0; f < 2; f++)
#pragma unroll
        for (int j = 0; j < 8; j++)
#pragma unroll
            for (int q = 0; q < 4; q++) acc[f][j][q] = 0.f;

    uint32_t aaddr[2];
#pragma unroll
    for (int f = 0; f < 2; f++)
        aaddr[f] = sm_b + (wm * 32 + f * 16 + ((quad & 1) << 3) + r8) * 528
                 + ((quad >> 1) << 4);
    uint32_t bbase[4];
#pragma unroll
    for (int jj = 0; jj < 4; jj++)
        bbase[jj] = (wn * 64 + jj * 16 + ((quad >> 1) << 3) + r8) * 144
                  + ((quad & 1) << 4);

    {
        const char* src = (const char*)(g_Woutp + (size_t)v0 * PAD_E);
#pragma unroll
        for (int i = 0; i < 5; i++) {
            int idx = tid + i * 512;
            if (idx < 2304) cp16(sm_b + LSB_OFF + idx * 16, src + idx * 16);
        }
        cp_commit();
    }
    {
        const uint32_t* src = (const uint32_t*)g_h1h;
#pragma unroll
        for (int i = 0; i < 32; i++) {
            int idx = tid + i * 512;
            int row = idx >> 7;
            int c32 = idx & 127;
            *(uint32_t*)(smem + row * 528 + c32 * 4) = src[idx];
        }
    }

#pragma unroll
    for (int c = 0; c < 4; c++) {
        if (c < 3) {
            const char* src =
                (const char*)(g_Woutp + ((size_t)(c + 1) * VSZ + v0) * PAD_E);
            uint32_t dst = sm_b + LSB_OFF + ((c + 1) & 1) * SB_STRIDE;
#pragma unroll
            for (int i = 0; i < 5; i++) {
                int idx = tid + i * 512;
                if (idx < 2304) cp16(dst + idx * 16, src + idx * 16);
            }
            cp_commit();
            cp_wait<1>();
        } else {
            cp_wait<0>();
        }
        __syncthreads();

        const uint32_t buf = sm_b + LSB_OFF + (c & 1) * SB_STRIDE;
#pragma unroll
        for (int ks = 0; ks < 4; ks++) {
            uint32_t af[2][4];
#pragma unroll
            for (int f = 0; f < 2; f++)
                ldsm_x4(af[f], aaddr[f] + c * 128 + ks * 32);
#pragma unroll
            for (int jj = 0; jj < 4; jj++) {
                uint32_t bf[4];
                ldsm_x4(bf, buf + bbase[jj] + ks * 32);
                mma_fp16(acc[0][2 * jj], af[0], bf[0], bf[1]);
                mma_fp16(acc[1][2 * jj], af[1], bf[0], bf[1]);
                mma_fp16(acc[0][2 * jj + 1], af[0], bf[2], bf[3]);
                mma_fp16(acc[1][2 * jj + 1], af[1], bf[2], bf[3]);
            }
        }
        __syncthreads();
    }

    float* stage = (float*)(smem + LSB_OFF);
    float rm = -1e30f, rs = 0.f;           // per-row softmax partials (tid<128)
#pragma unroll
    for (int cg = 0; cg < 4; cg++) {
        if (wn == cg) {
#pragma unroll
            for (int f = 0; f < 2; f++)
#pragma unroll
                for (int j = 0; j < 8; j++)
#pragma unroll
                    for (int q = 0; q < 4; q++) {
                        int row = wm * 32 + f * 16 + g + 8 * (q >> 1);
                        int col = 8 * j + 2 * t + (q & 1);
                        stage[row * 65 + col] = acc[f][j][q];
                    }
        }
        __syncthreads();
#pragma unroll
        for (int i = 0; i < 16; i++) {
            int idx = tid + i * 512;
            int row = idx >> 6;
            int col = idx & 63;
            out[(size_t)row * VSZ + v0 + cg * 64 + col] =
                stage[row * 65 + col] + bout[v0 + cg * 64 + col];
        }
        if (tid < 128) {
            float lm = rm;
            for (int col = 0; col < 64; col++)
                lm = fmaxf(lm, stage[tid * 65 + col] + bout[v0 + cg * 64 + col]);
            float sc = rs * expf(rm - lm);
            for (int col = 0; col < 64; col++)
                sc += expf(stage[tid * 65 + col] + bout[v0 + cg * 64 + col] - lm);
            rm = lm;
            rs = sc;
        }
        __syncthreads();
    }
    if (tid < 128) {
        g_lmz[(tid * NVB + blockIdx.x) * 2] = rm;
        g_lmz[(tid * NVB + blockIdx.x) * 2 + 1] = rs;
    }
}

// ---------------- K8: log_softmax via partials (single pass) --------------
__global__ __launch_bounds__(1024)
void logsoftmax_kernel(float* __restrict__ out) {
    const int b = blockIdx.x;
    const int tid = threadIdx.x;  // 1024
    __shared__ float red[1024];
    float4* row4 = (float4*)(out + (size_t)b * VSZ);

    float lm = -1e30f;
    if (tid < NVB) lm = g_lmz[(b * NVB + tid) * 2];
    red[tid] = lm;
    __syncthreads();
    for (int d = 512; d > 0; d >>= 1) {
        if (tid < d) red[tid] = fmaxf(red[tid], red[tid + d]);
        __syncthreads();
    }
    float M = red[0];
    __syncthreads();
    float sv = 0.f;
    if (tid < NVB)
        sv = g_lmz[(b * NVB + tid) * 2 + 1] * expf(lm - M);
    red[tid] = sv;
    __syncthreads();
    for (int d = 512; d > 0; d >>= 1) {
        if (tid < d) red[tid] += red[tid + d];
        __syncthreads();
    }
    float lse = M + logf(red[0]);
    for (int v = tid; v < 8000; v += 1024) {
        float4 x = row4[v];
        x.x -= lse; x.y -= lse; x.z -= lse; x.w -= lse;
        row4[v] = x;
    }
}

// ---------------- launch ----------------
extern "C" void kernel_launch(void* const* d_in, const int* in_sizes, int n_in,
                              void* d_out, int out_size) {
    const int* inp = (const int*)d_in[0];
    const float* hidden = (const float*)d_in[1];
    const float* enc = (const float*)d_in[2];
    const float* emb = (const float*)d_in[3];
    const float* W1 = (const float*)d_in[4];
    const float* W2 = (const float*)d_in[5];
    const float* W3 = (const float*)d_in[6];
    const float* b2 = (const float*)d_in[7];
    const float* b3 = (const float*)d_in[8];
    const float* V = (const float*)d_in[9];
    const float* Wih0 = (const float*)d_in[10];
    const float* Whh0 = (const float*)d_in[11];
    const float* bih0 = (const float*)d_in[12];
    const float* bhh0 = (const float*)d_in[13];
    const float* Wih1 = (const float*)d_in[14];
    const float* Whh1 = (const float*)d_in[15];
    const float* bih1 = (const float*)d_in[16];
    const float* bhh1 = (const float*)d_in[17];
    const float* Wout = (const float*)d_in[18];
    const float* bout = (const float*)d_in[19];

    float* out = (float*)d_out;
    float* hid_out = out + (size_t)Bd * VSZ;

    cudaFuncSetAttribute(scores_mma_kernel,
                         cudaFuncAttributeMaxDynamicSharedMemorySize, SC_SMEM);
    cudaFuncSetAttribute(logits_mma_kernel,
                         cudaFuncAttributeMaxDynamicSharedMemorySize, LG_SMEM);
    cudaFuncSetAttribute(res_kernel,
                         cudaFuncAttributeMaxDynamicSharedMemorySize, RES_SMEM);

    prep_w1_kernel<<<Hd, Hd>>>(W1);
    prep_wout_kernel<<<8000, 256>>>(Wout);
    w2h_kernel<<<Bd, 512>>>(hidden, W2, b2);
    scores_mma_kernel<<<Bd * NCH, 256, SC_SMEM>>>(enc, V);
    cat_kernel<<<Bd, 256>>>(inp, emb);
    res_kernel<<<16, 512, RES_SMEM>>>(W3, b3);
    float* g_res_p;
    cudaGetSymbolAddress((void**)&g_res_p, g_res);
    float* g_x1_p;
    cudaGetSymbolAddress((void**)&g_x1_p, g_x1);
    gru_gates_kernel<<<dim3(12, 8), 512>>>(g_res_p, hidden,
                                           Wih0, Whh0, bih0, bhh0);
    gru_combine_kernel<<<64, 512>>>(hidden, 0, hid_out);
    gru_gates_kernel<<<dim3(12, 8), 512>>>(g_x1_p, hidden + Bd * Hd,
                                           Wih1, Whh1, bih1, bhh1);
    gru_combine_kernel<<<64, 512>>>(hidden + Bd * Hd, 1, hid_out);
    logits_mma_kernel<<<NVB, 512, LG_SMEM>>>(bout, out);
    logsoftmax_kernel<<<Bd, 1024>>>(out);
}

// round 12
// speedup vs baseline: 1.2935x; 1.0239x over previous
#include <cuda_runtime.h>
#include <cuda_fp16.h>
#include <cstdint>

#define Bd 128
#define Sd 2048
#define Hd 256
#define Ed 256
#define VSZ 32000
#define NCH 32                              // 64-row S-chunks per batch
#define NVB 125                             // vocab blocks of 256

// ---------------- scratch (device globals; no allocation) ----------------
__device__ float g_w2h[Bd * Hd];
__device__ float g_mz[2 * Bd * NCH];
__device__ float g_XaP[NCH * Bd * Hd];
__device__ float g_cat[Bd * 512];
__device__ float g_res[Bd * Hd];
__device__ float g_gi[Bd * 768];            // cell 0 gates
__device__ float g_gh[Bd * 768];
__device__ float g_gi2[Bd * 768];           // cell 1 gates
__device__ float g_gh2[Bd * 768];
__device__ float g_lmz[Bd * NVB * 2];
__device__ __align__(16) __half g_h1h[Bd * Hd];

#define PAD_E 72
#define CH_HALF_E (Hd * PAD_E)              // 36864 B per chunk
__device__ __align__(16) __half g_W1p[4 * CH_HALF_E];
__device__ __align__(16) __half g_Woutp[4 * VSZ * PAD_E];

// ---------------- helpers ----------------
__device__ __forceinline__ float fast_tanh(float x) {
    float y;
    asm("tanh.approx.f32 %0, %1;" : "=f"(y) : "f"(x));
    return y;
}
__device__ __forceinline__ uint32_t smem_u32(const void* p) {
    uint32_t a;
    asm("{ .reg .u64 t; cvta.to.shared.u64 t, %1; cvt.u32.u64 %0, t; }"
        : "=r"(a) : "l"(p));
    return a;
}
__device__ __forceinline__ void cp16(uint32_t dst, const void* src) {
    asm volatile("cp.async.cg.shared.global [%0], [%1], 16;"
                 :: "r"(dst), "l"(src) : "memory");
}
__device__ __forceinline__ void cp_commit() {
    asm volatile("cp.async.commit_group;" ::: "memory");
}
template <int N>
__device__ __forceinline__ void cp_wait() {
    asm volatile("cp.async.wait_group %0;" :: "n"(N) : "memory");
}
__device__ __forceinline__ void mma_fp16(float* d, const uint32_t* a,
                                         uint32_t b0, uint32_t b1) {
    asm volatile(
        "mma.sync.aligned.m16n8k16.row.col.f32.f16.f16.f32 "
        "{%0,%1,%2,%3}, {%4,%5,%6,%7}, {%8,%9}, {%0,%1,%2,%3};"
        : "+f"(d[0]), "+f"(d[1]), "+f"(d[2]), "+f"(d[3])
        : "r"(a[0]), "r"(a[1]), "r"(a[2]), "r"(a[3]), "r"(b0), "r"(b1));
}
__device__ __forceinline__ void ldsm_x4(uint32_t* r, uint32_t addr) {
    asm volatile(
        "ldmatrix.sync.aligned.m8n8.x4.shared.b16 {%0,%1,%2,%3}, [%4];"
        : "=r"(r[0]), "=r"(r[1]), "=r"(r[2]), "=r"(r[3]) : "r"(addr));
}

// ---------------- K0: merged prep (Wout pack | W1 pack | w2h) -------------
// grid: [0,8000) wout pack; [8000,8256) W1 pack; [8256,8288) w2h slices.
__global__ __launch_bounds__(256)
void prep_merge_kernel(const float* __restrict__ W1,
                       const float* __restrict__ Wout,
                       const float* __restrict__ hidden,
                       const float* __restrict__ W2,
                       const float* __restrict__ b2) {
    const int bid = blockIdx.x;
    const int tid = threadIdx.x;
    if (bid < 8000) {
        int idx4 = (bid * 256 + tid) * 4;
        int v = idx4 >> 8;
        int k = idx4 & 255;
        float4 x = *(const float4*)(Wout + (size_t)v * Hd + k);
        __half2 a = {__float2half_rn(x.x), __float2half_rn(x.y)};
        __half2 b = {__float2half_rn(x.z), __float2half_rn(x.w)};
        uint2 w;
        w.x = *(uint32_t*)&a;
        w.y = *(uint32_t*)&b;
        *(uint2*)&g_Woutp[(size_t)(k >> 6) * VSZ * PAD_E +
                          (size_t)v * PAD_E + (k & 63)] = w;
    } else if (bid < 8256) {
        int n = bid - 8000;
        int k = tid;
        float x = W1[k * Hd + n];
        g_W1p[(k >> 6) * CH_HALF_E + n * PAD_E + (k & 63)] = __float2half_rn(x);
    } else {
        // w2h slice: wb in [0,32): n0 = (wb&3)*64, b0 = (wb>>2)*16
        int wb = bid - 8256;
        int n0 = (wb & 3) * 64;
        int b0 = (wb >> 2) * 16;
        __shared__ float sh[16][260];
        for (int i = tid; i < 16 * 256; i += 256) {
            int bb = i >> 8;
            int k = i & 255;
            sh[bb][k] = hidden[(size_t)(Bd + b0 + bb) * Hd + k];
        }
        __syncthreads();
        int nn = tid & 63;
        int bq = tid >> 6;  // 0..3
        float acc[4] = {0.f, 0.f, 0.f, 0.f};
#pragma unroll 8
        for (int j = 0; j < 256; j++) {
            float w = W2[j * Hd + n0 + nn];
#pragma unroll
            for (int u = 0; u < 4; u++) acc[u] += sh[bq + 4 * u][j] * w;
        }
        float bias = b2[n0 + nn];
#pragma unroll
        for (int u = 0; u < 4; u++)
            g_w2h[(size_t)(b0 + bq + 4 * u) * Hd + n0 + nn] = acc[u] + bias;
    }
}

// ---------------- K2: scores + local softmax + partial Xa numerator -------
#define SA_HI 0
#define SB_OFF 33792
#define SB_STRIDE 36864
#define SC_SMEM (33792 + 2 * 36864)
__global__ __launch_bounds__(256, 2)
void scores_mma_kernel(const float* __restrict__ enc,
                       const float* __restrict__ Vv) {
    extern __shared__ __align__(16) char smem[];
    const uint32_t sm_b = smem_u32(smem);
    const int tid = threadIdx.x;
    const int wid = tid >> 5;
    const int lane = tid & 31;
    const int g = lane >> 2;
    const int t = lane & 3;
    const int wm = wid >> 2;
    const int wn = wid & 3;
    const int quad = lane >> 3;
    const int r8 = lane & 7;
    const int b = blockIdx.x >> 5;
    const int chunk = blockIdx.x & (NCH - 1);
    const int m0 = blockIdx.x * 64;
    const float* encb = enc + (size_t)m0 * Hd;

    float acc[2][8][4];
#pragma unroll
    for (int f = 0; f < 2; f++)
#pragma unroll
        for (int j = 0; j < 8; j++)
#pragma unroll
            for (int q = 0; q < 4; q++) acc[f][j][q] = 0.f;

    uint32_t aaddr[2];
#pragma unroll
    for (int f = 0; f < 2; f++)
        aaddr[f] = sm_b + (wm * 32 + f * 16 + ((quad & 1) << 3) + r8) * 528
                 + ((quad >> 1) << 4);
    uint32_t bbase[4];
#pragma unroll
    for (int jj = 0; jj < 4; jj++)
        bbase[jj] = (wn * 64 + jj * 16 + ((quad >> 1) << 3) + r8) * 144
                  + ((quad & 1) << 4);

    {
        const char* src = (const char*)g_W1p;
#pragma unroll
        for (int i = 0; i < 9; i++) {
            int idx = tid + i * 256;
            cp16(sm_b + SB_OFF + idx * 16, src + idx * 16);
        }
        cp_commit();
    }
    {
#pragma unroll
        for (int i = 0; i < 16; i++) {
            int idx = tid + i * 256;
            int row = idx >> 6;
            int kp = idx & 63;
            float4 v = *(const float4*)(encb + (size_t)row * Hd + kp * 4);
            __half2 h0 = {__float2half_rn(v.x), __float2half_rn(v.y)};
            __half2 h1 = {__float2half_rn(v.z), __float2half_rn(v.w)};
            uint2 w;
            w.x = *(uint32_t*)&h0;
            w.y = *(uint32_t*)&h1;
            *(uint2*)(smem + SA_HI + row * 528 + kp * 8) = w;
        }
    }

#pragma unroll
    for (int c = 0; c < 4; c++) {
        if (c < 3) {
            const char* src = (const char*)(g_W1p + (size_t)(c + 1) * CH_HALF_E);
            uint32_t dst = sm_b + SB_OFF + ((c + 1) & 1) * SB_STRIDE;
#pragma unroll
            for (int i = 0; i < 9; i++) {
                int idx = tid + i * 256;
                cp16(dst + idx * 16, src + idx * 16);
            }
            cp_commit();
            cp_wait<1>();
        } else {
            cp_wait<0>();
        }
        __syncthreads();

        const uint32_t buf = sm_b + SB_OFF + (c & 1) * SB_STRIDE;
#pragma unroll
        for (int ks = 0; ks < 4; ks++) {
            uint32_t af[2][4];
#pragma unroll
            for (int f = 0; f < 2; f++)
                ldsm_x4(af[f], aaddr[f] + c * 128 + ks * 32);
#pragma unroll
            for (int jj = 0; jj < 4; jj++) {
                uint32_t bf[4];
                ldsm_x4(bf, buf + bbase[jj] + ks * 32);
                mma_fp16(acc[0][2 * jj], af[0], bf[0], bf[1]);
                mma_fp16(acc[1][2 * jj], af[1], bf[0], bf[1]);
                mma_fp16(acc[0][2 * jj + 1], af[0], bf[2], bf[3]);
                mma_fp16(acc[1][2 * jj + 1], af[1], bf[2], bf[3]);
            }
        }
        __syncthreads();
    }

    float* EP = (float*)(smem + SB_OFF);
    float* sw2 = EP;
    float* sV = EP + 256;
    float* sp = EP + 512;
    float* red = EP + 768;
    float* e_arr = EP + 832;
    sw2[tid] = g_w2h[b * Hd + tid];
    sV[tid] = Vv[tid];
    __syncthreads();

    float p[2][2] = {{0.f, 0.f}, {0.f, 0.f}};
#pragma unroll
    for (int f = 0; f < 2; f++)
#pragma unroll
        for (int j = 0; j < 8; j++) {
            int cc = wn * 64 + 8 * j + 2 * t;
            float v0 = sV[cc], v1 = sV[cc + 1];
            float w0 = sw2[cc], w1 = sw2[cc + 1];
            p[f][0] += v0 * fast_tanh(acc[f][j][0] + w0)
                     + v1 * fast_tanh(acc[f][j][1] + w1);
            p[f][1] += v0 * fast_tanh(acc[f][j][2] + w0)
                     + v1 * fast_tanh(acc[f][j][3] + w1);
        }
#pragma unroll
    for (int f = 0; f < 2; f++)
#pragma unroll
        for (int u = 0; u < 2; u++) {
            float v = p[f][u];
            v += __shfl_xor_sync(0xffffffffu, v, 1);
            v += __shfl_xor_sync(0xffffffffu, v, 2);
            if (t == 0) {
                int r = wm * 32 + f * 16 + g + 8 * u;
                sp[wn * 64 + r] = v;
            }
        }
    __syncthreads();

    float sc = 0.f;
    if (tid < 64) {
        sc = sp[tid] + sp[64 + tid] + sp[128 + tid] + sp[192 + tid];
        red[tid] = sc;
    }
    __syncthreads();
    for (int d = 32; d > 0; d >>= 1) {
        if (tid < d) red[tid] = fmaxf(red[tid], red[tid + d]);
        __syncthreads();
    }
    float mloc = red[0];
    __syncthreads();
    if (tid < 64) {
        float e = expf(sc - mloc);
        e_arr[tid] = e;
        red[tid] = e;
    }
    __syncthreads();
    for (int d = 32; d > 0; d >>= 1) {
        if (tid < d) red[tid] += red[tid + d];
        __syncthreads();
    }
    if (tid == 0) {
        g_mz[2 * blockIdx.x] = mloc;
        g_mz[2 * blockIdx.x + 1] = red[0];
    }
    __syncthreads();

    float a2 = 0.f;
#pragma unroll 8
    for (int s = 0; s < 64; s++) {
        __half hv = *(const __half*)(smem + SA_HI + s * 528 + tid * 2);
        a2 += e_arr[s] * __half2float(hv);
    }
    g_XaP[((size_t)chunk * Bd + b) * Hd + tid] = a2;
}

// ---------------- K3: cat = [emb[inp]; Xa-combined] ----------------
__global__ void cat_kernel(const int* __restrict__ inp,
                           const float* __restrict__ emb) {
    const int b = blockIdx.x;
    const int tid = threadIdx.x;  // 256
    int token = inp[b];
    g_cat[b * 512 + tid] = emb[(size_t)token * Ed + tid];
    float M = -1e30f;
#pragma unroll
    for (int i = 0; i < NCH; i++)
        M = fmaxf(M, g_mz[2 * (b * NCH + i)]);
    float Z = 0.f, X = 0.f;
#pragma unroll
    for (int i = 0; i < NCH; i++) {
        float w = expf(g_mz[2 * (b * NCH + i)] - M);
        Z += w * g_mz[2 * (b * NCH + i) + 1];
        X += w * g_XaP[((size_t)i * Bd + b) * Hd + tid];
    }
    g_cat[b * 512 + 256 + tid] = X / Z;
}

// ---------------- K4: res = cat @ W3 + b3 (64 CTAs: 16 n x 4 b) ----------
#define RES_SMEM ((16 * 524 + 32 * 520) * 4)
__global__ __launch_bounds__(512)
void res_kernel(const float* __restrict__ W3, const float* __restrict__ b3) {
    extern __shared__ float rsm[];
    float* w3t = rsm;                // 16 x 524
    float* cs = rsm + 16 * 524;      // 32 x 520
    const int n0 = (blockIdx.x & 15) * 16;
    const int bt = blockIdx.x >> 4;
    const int tid = threadIdx.x;
    const int nn = tid & 15;
    const int bq = tid >> 4;

    for (int idx = tid; idx < 512 * 16; idx += 512) {
        int k = idx >> 4;
        int n = idx & 15;
        w3t[n * 524 + k] = W3[(size_t)k * Hd + n0 + n];
    }
    for (int idx = tid; idx < 32 * 512; idx += 512) {
        int bb = idx >> 9;
        int k = idx & 511;
        cs[bb * 520 + k] = g_cat[(size_t)(bt * 32 + bb) * 512 + k];
    }
    __syncthreads();
    float acc = 0.f;
#pragma unroll 8
    for (int k4 = 0; k4 < 128; k4++) {
        float4 cv = *(const float4*)&cs[bq * 520 + k4 * 4];
        float4 wv = *(const float4*)&w3t[nn * 524 + k4 * 4];
        acc += cv.x * wv.x + cv.y * wv.y + cv.z * wv.z + cv.w * wv.w;
    }
    g_res[(size_t)(bt * 32 + bq) * Hd + n0 + nn] = acc + b3[n0 + nn];
}

// ---------------- K5: GRU gate GEMVs; cell 1 inlines combine0 -------------
__global__ __launch_bounds__(512)
void gru_gates_kernel(const float* __restrict__ hidden,
                      const float* __restrict__ Wih,
                      const float* __restrict__ Whh,
                      const float* __restrict__ bih,
                      const float* __restrict__ bhh,
                      int cell,
                      float* __restrict__ hid_out) {
    const int n0 = blockIdx.x * 64;
    const int b0 = blockIdx.y * 16;
    const int tid = threadIdx.x;
    __shared__ float xs[16][260], hs[16][260];
    if (cell == 0) {
        for (int i = tid; i < 16 * 256; i += 512) {
            int bb = i >> 8;
            int k = i & 255;
            xs[bb][k] = g_res[(size_t)(b0 + bb) * Hd + k];
            hs[bb][k] = hidden[(size_t)(b0 + bb) * Hd + k];
        }
    } else {
        // inline combine0: h0 from cell-0 gates
        for (int i = tid; i < 16 * 256; i += 512) {
            int bb = i >> 8;
            int j = i & 255;
            int b = b0 + bb;
            float gir = g_gi[(size_t)b * 768 + j];
            float ghr = g_gh[(size_t)b * 768 + j];
            float giz = g_gi[(size_t)b * 768 + 256 + j];
            float ghz = g_gh[(size_t)b * 768 + 256 + j];
            float gin = g_gi[(size_t)b * 768 + 512 + j];
            float ghn = g_gh[(size_t)b * 768 + 512 + j];
            float r = 1.f / (1.f + expf(-(gir + ghr)));
            float z = 1.f / (1.f + expf(-(giz + ghz)));
            float n = tanhf(gin + r * ghn);
            float h = hidden[(size_t)b * Hd + j];
            float hn = (1.f - z) * n + z * h;
            xs[bb][j] = hn;
            hs[bb][j] = hidden[(size_t)(Bd + b) * Hd + j];
            if (blockIdx.x == 0) hid_out[(size_t)b * Hd + j] = hn;
        }
    }
    __syncthreads();
    const int bb = tid & 15;
    const int g2 = tid >> 4;
    float* gi_out = (cell == 0) ? g_gi : g_gi2;
    float* gh_out = (cell == 0) ? g_gh : g_gh2;
#pragma unroll
    for (int gg = 0; gg < 2; gg++) {
        int gr = n0 + g2 + gg * 32;
        const float4* wi = (const float4*)(Wih + (size_t)gr * Hd);
        const float4* wh = (const float4*)(Whh + (size_t)gr * Hd);
        float gi = bih[gr], gh = bhh[gr];
#pragma unroll 8
        for (int k4 = 0; k4 < 64; k4++) {
            float4 a = wi[k4];
            float4 c = wh[k4];
            float4 xv = *(const float4*)&xs[bb][k4 * 4];
            float4 hv = *(const float4*)&hs[bb][k4 * 4];
            gi += a.x * xv.x + a.y * xv.y + a.z * xv.z + a.w * xv.w;
            gh += c.x * hv.x + c.y * hv.y + c.z * hv.z + c.w * hv.w;
        }
        gi_out[(size_t)(b0 + bb) * 768 + gr] = gi;
        gh_out[(size_t)(b0 + bb) * 768 + gr] = gh;
    }
}

// ---------------- K6: combine cell 1 -> hid_out + fp16 h1 ----------------
__global__ void gru_combine1_kernel(const float* __restrict__ hidden,
                                    float* __restrict__ hid_out) {
    int idx = blockIdx.x * 512 + threadIdx.x;  // 32768
    int b = idx >> 8;
    int j = idx & 255;
    float gir = g_gi2[(size_t)b * 768 + j];
    float ghr = g_gh2[(size_t)b * 768 + j];
    float giz = g_gi2[(size_t)b * 768 + 256 + j];
    float ghz = g_gh2[(size_t)b * 768 + 256 + j];
    float gin = g_gi2[(size_t)b * 768 + 512 + j];
    float ghn = g_gh2[(size_t)b * 768 + 512 + j];
    float r = 1.f / (1.f + expf(-(gir + ghr)));
    float z = 1.f / (1.f + expf(-(giz + ghz)));
    float n = tanhf(gin + r * ghn);
    float h = hidden[(size_t)(Bd + b) * Hd + j];
    float hn = (1.f - z) * n + z * h;
    hid_out[(size_t)(Bd + b) * Hd + j] = hn;
    g_h1h[(size_t)b * Hd + j] = __float2half_rn(hn);
}

// ---------------- K7: logits via fp16 mma + ldmatrix + softmax partials ---
#define LSB_OFF 67584
#define LG_SMEM (67584 + 2 * 36864)
__global__ __launch_bounds__(512, 1)
void logits_mma_kernel(const float* __restrict__ bout,
                       float* __restrict__ out) {
    extern __shared__ __align__(16) char smem[];
    const uint32_t sm_b = smem_u32(smem);
    const int tid = threadIdx.x;
    const int wid = tid >> 5;
    const int lane = tid & 31;
    const int g = lane >> 2;
    const int t = lane & 3;
    const int wm = wid >> 2;
    const int wn = wid & 3;
    const int quad = lane >> 3;
    const int r8 = lane & 7;
    const int v0 = blockIdx.x * 256;

    float acc[2][8][4];
#pragma unroll
    for (int f = 0; f < 2; f++)
#pragma unroll
        for (int j = 0; j < 8; j++)
#pragma unroll
            for (int q = 0; q < 4; q++) acc[f][j][q] = 0.f;

    uint32_t aaddr[2];
#pragma unroll
    for (int f = 0; f < 2; f++)
        aaddr[f] = sm_b + (wm * 32 + f * 16 + ((quad & 1) << 3) + r8) * 528
                 + ((quad >> 1) << 4);
    uint32_t bbase[4];
#pragma unroll
    for (int jj = 0; jj < 4; jj++)
        bbase[jj] = (wn * 64 + jj * 16 + ((quad >> 1) << 3) + r8) * 144
                  + ((quad & 1) << 4);

    {
        const char* src = (const char*)(g_Woutp + (size_t)v0 * PAD_E);
#pragma unroll
        for (int i = 0; i < 5; i++) {
            int idx = tid + i * 512;
            if (idx < 2304) cp16(sm_b + LSB_OFF + idx * 16, src + idx * 16);
        }
        cp_commit();
    }
    {
        const uint32_t* src = (const uint32_t*)g_h1h;
#pragma unroll
        for (int i = 0; i < 32; i++) {
            int idx = tid + i * 512;
            int row = idx >> 7;
            int c32 = idx & 127;
            *(uint32_t*)(smem + row * 528 + c32 * 4) = src[idx];
        }
    }

#pragma unroll
    for (int c = 0; c < 4; c++) {
        if (c < 3) {
            const char* src =
                (const char*)(g_Woutp + ((size_t)(c + 1) * VSZ + v0) * PAD_E);
            uint32_t dst = sm_b + LSB_OFF + ((c + 1) & 1) * SB_STRIDE;
#pragma unroll
            for (int i = 0; i < 5; i++) {
                int idx = tid + i * 512;
                if (idx < 2304) cp16(dst + idx * 16, src + idx * 16);
            }
            cp_commit();
            cp_wait<1>();
        } else {
            cp_wait<0>();
        }
        __syncthreads();

        const uint32_t buf = sm_b + LSB_OFF + (c & 1) * SB_STRIDE;
#pragma unroll
        for (int ks = 0; ks < 4; ks++) {
            uint32_t af[2][4];
#pragma unroll
            for (int f = 0; f < 2; f++)
                ldsm_x4(af[f], aaddr[f] + c * 128 + ks * 32);
#pragma unroll
            for (int jj = 0; jj < 4; jj++) {
                uint32_t bf[4];
                ldsm_x4(bf, buf + bbase[jj] + ks * 32);
                mma_fp16(acc[0][2 * jj], af[0], bf[0], bf[1]);
                mma_fp16(acc[1][2 * jj], af[1], bf[0], bf[1]);
                mma_fp16(acc[0][2 * jj + 1], af[0], bf[2], bf[3]);
                mma_fp16(acc[1][2 * jj + 1], af[1], bf[2], bf[3]);
            }
        }
        __syncthreads();
    }

    float* stage = (float*)(smem + LSB_OFF);
    float rm = -1e30f, rs = 0.f;
#pragma unroll
    for (int cg = 0; cg < 4; cg++) {
        if (wn == cg) {
#pragma unroll
            for (int f = 0; f < 2; f++)
#pragma unroll
                for (int j = 0; j < 8; j++)
#pragma unroll
                    for (int q = 0; q < 4; q++) {
                        int row = wm * 32 + f * 16 + g + 8 * (q >> 1);
                        int col = 8 * j + 2 * t + (q & 1);
                        stage[row * 65 + col] = acc[f][j][q];
                    }
        }
        __syncthreads();
#pragma unroll
        for (int i = 0; i < 16; i++) {
            int idx = tid + i * 512;
            int row = idx >> 6;
            int col = idx & 63;
            out[(size_t)row * VSZ + v0 + cg * 64 + col] =
                stage[row * 65 + col] + bout[v0 + cg * 64 + col];
        }
        if (tid < 128) {
            float lm = rm;
            for (int col = 0; col < 64; col++)
                lm = fmaxf(lm, stage[tid * 65 + col] + bout[v0 + cg * 64 + col]);
            float sc = rs * expf(rm - lm);
            for (int col = 0; col < 64; col++)
                sc += expf(stage[tid * 65 + col] + bout[v0 + cg * 64 + col] - lm);
            rm = lm;
            rs = sc;
        }
        __syncthreads();
    }
    if (tid < 128) {
        g_lmz[(tid * NVB + blockIdx.x) * 2] = rm;
        g_lmz[(tid * NVB + blockIdx.x) * 2 + 1] = rs;
    }
}

// ---------------- K8: log_softmax via partials (single pass) --------------
__global__ __launch_bounds__(1024)
void logsoftmax_kernel(float* __restrict__ out) {
    const int b = blockIdx.x;
    const int tid = threadIdx.x;
    __shared__ float red[1024];
    float4* row4 = (float4*)(out + (size_t)b * VSZ);

    float lm = -1e30f;
    if (tid < NVB) lm = g_lmz[(b * NVB + tid) * 2];
    red[tid] = lm;
    __syncthreads();
    for (int d = 512; d > 0; d >>= 1) {
        if (tid < d) red[tid] = fmaxf(red[tid], red[tid + d]);
        __syncthreads();
    }
    float M = red[0];
    __syncthreads();
    float sv = 0.f;
    if (tid < NVB)
        sv = g_lmz[(b * NVB + tid) * 2 + 1] * expf(lm - M);
    red[tid] = sv;
    __syncthreads();
    for (int d = 512; d > 0; d >>= 1) {
        if (tid < d) red[tid] += red[tid + d];
        __syncthreads();
    }
    float lse = M + logf(red[0]);
    for (int v = tid; v < 8000; v += 1024) {
        float4 x = row4[v];
        x.x -= lse; x.y -= lse; x.z -= lse; x.w -= lse;
        row4[v] = x;
    }
}

// ---------------- launch ----------------
extern "C" void kernel_launch(void* const* d_in, const int* in_sizes, int n_in,
                              void* d_out, int out_size) {
    const int* inp = (const int*)d_in[0];
    const float* hidden = (const float*)d_in[1];
    const float* enc = (const float*)d_in[2];
    const float* emb = (const float*)d_in[3];
    const float* W1 = (const float*)d_in[4];
    const float* W2 = (const float*)d_in[5];
    const float* W3 = (const float*)d_in[6];
    const float* b2 = (const float*)d_in[7];
    const float* b3 = (const float*)d_in[8];
    const float* V = (const float*)d_in[9];
    const float* Wih0 = (const float*)d_in[10];
    const float* Whh0 = (const float*)d_in[11];
    const float* bih0 = (const float*)d_in[12];
    const float* bhh0 = (const float*)d_in[13];
    const float* Wih1 = (const float*)d_in[14];
    const float* Whh1 = (const float*)d_in[15];
    const float* bih1 = (const float*)d_in[16];
    const float* bhh1 = (const float*)d_in[17];
    const float* Wout = (const float*)d_in[18];
    const float* bout = (const float*)d_in[19];

    float* out = (float*)d_out;
    float* hid_out = out + (size_t)Bd * VSZ;

    cudaFuncSetAttribute(scores_mma_kernel,
                         cudaFuncAttributeMaxDynamicSharedMemorySize, SC_SMEM);
    cudaFuncSetAttribute(logits_mma_kernel,
                         cudaFuncAttributeMaxDynamicSharedMemorySize, LG_SMEM);
    cudaFuncSetAttribute(res_kernel,
                         cudaFuncAttributeMaxDynamicSharedMemorySize, RES_SMEM);

    prep_merge_kernel<<<8288, 256>>>(W1, Wout, hidden, W2, b2);
    scores_mma_kernel<<<Bd * NCH, 256, SC_SMEM>>>(enc, V);
    cat_kernel<<<Bd, 256>>>(inp, emb);
    res_kernel<<<64, 512, RES_SMEM>>>(W3, b3);
    gru_gates_kernel<<<dim3(12, 8), 512>>>(hidden, Wih0, Whh0, bih0, bhh0,
                                           0, hid_out);
    gru_gates_kernel<<<dim3(12, 8), 512>>>(hidden, Wih1, Whh1, bih1, bhh1,
                                           1, hid_out);
    gru_combine1_kernel<<<64, 512>>>(hidden, hid_out);
    logits_mma_kernel<<<NVB, 512, LG_SMEM>>>(bout, out);
    logsoftmax_kernel<<<Bd, 1024>>>(out);
}